// round 12
// baseline (speedup 1.0000x reference)
#include <cuda_runtime.h>
#include <math.h>

#define BG 1024
#define PP 128
#define KN 20
#define EPSB 1e-5f

typedef unsigned long long u64;

// ---- persistent scratch ----
__device__ unsigned int g_idx1[BG * PP * 5];   // 20 packed neighbor bytes per point
__device__ float g_stats[64];                  // sum1/sq1/sum2/sq2

__global__ void k0_zero() { if (threadIdx.x < 64) g_stats[threadIdx.x] = 0.f; }

// embed 7-bit index in mantissa LSBs -> unique keys, register-only top-K
__device__ __forceinline__ float embed(float d2, int j) {
    return __uint_as_float((__float_as_uint(d2) & 0xFFFFFF80u) | (unsigned)j);
}

// packed f32x2 helpers (sm_100+)
__device__ __forceinline__ u64 pk2(float a, float b) {
    u64 r; asm("mov.b64 %0,{%1,%2};" : "=l"(r) : "f"(a), "f"(b)); return r;
}
__device__ __forceinline__ void upk2(float& a, float& b, u64 v) {
    asm("mov.b64 {%0,%1},%2;" : "=f"(a), "=f"(b) : "l"(v));
}
__device__ __forceinline__ u64 fma2(u64 a, u64 b, u64 c) {
    u64 d; asm("fma.rn.f32x2 %0,%1,%2,%3;" : "=l"(d) : "l"(a), "l"(b), "l"(c)); return d;
}
__device__ __forceinline__ u64 add2(u64 a, u64 b) {
    u64 d; asm("add.rn.f32x2 %0,%1,%2;" : "=l"(d) : "l"(a), "l"(b)); return d;
}

// register-only sorted top-20 insert (branch-free bubble network)
__device__ __forceinline__ void ins20(float (&kd)[KN], float dv) {
    kd[KN - 1] = fminf(kd[KN - 1], dv);
#pragma unroll
    for (int p = KN - 1; p > 0; --p) {
        float lo = fminf(kd[p - 1], kd[p]);
        float hi = fmaxf(kd[p - 1], kd[p]);
        kd[p - 1] = lo; kd[p] = hi;
    }
}

// ------------------------------------------------------------------
// K1: kNN on pos (2 lists, 4 candidates/iter) + BN1 pre-activation stats
__global__ __launch_bounds__(128) void k1_knn_stats(
    const float* __restrict__ pos,
    const float* __restrict__ w1, const float* __restrict__ b1)
{
    __shared__ float spx[PP], spy[PP], spz[PP], sn[PP];
    __shared__ float v1s[PP * 17];
    __shared__ float w1u[48], w1v[48], b1s[16];
    __shared__ float wpart[4][32];

    int b = blockIdx.x, t = threadIdx.x;
    float px = pos[(b * PP + t) * 3 + 0];
    float py = pos[(b * PP + t) * 3 + 1];
    float pz = pos[(b * PP + t) * 3 + 2];
    spx[t] = px; spy[t] = py; spz[t] = pz;
    if (t < 48) { w1u[t] = w1[t] - w1[t + 48]; w1v[t] = w1[t + 48]; }
    if (t < 16) b1s[t] = b1[t];
    float ni = px * px + py * py + pz * pz;
    sn[t] = ni;
    __syncthreads();

    float kA[KN], kB[KN];
#pragma unroll
    for (int k = 0; k < KN; ++k) { kA[k] = 1e38f; kB[k] = 1e38f; }
#pragma unroll 1
    for (int j = 0; j < PP; j += 4) {
        float d0 = ni + sn[j]     - 2.f * (px * spx[j]     + py * spy[j]     + pz * spz[j]);
        float d1 = ni + sn[j + 1] - 2.f * (px * spx[j + 1] + py * spy[j + 1] + pz * spz[j + 1]);
        float d2 = ni + sn[j + 2] - 2.f * (px * spx[j + 2] + py * spy[j + 2] + pz * spz[j + 2]);
        float d3 = ni + sn[j + 3] - 2.f * (px * spx[j + 3] + py * spy[j + 3] + pz * spz[j + 3]);
        if (j == t)     d0 = 1e30f;
        if (j + 1 == t) d1 = 1e30f;
        if (j + 2 == t) d2 = 1e30f;
        if (j + 3 == t) d3 = 1e30f;
        ins20(kA, embed(d0, j));
        ins20(kA, embed(d2, j + 2));
        ins20(kB, embed(d1, j + 1));
        ins20(kB, embed(d3, j + 3));
    }

    float u1[16];
#pragma unroll
    for (int c = 0; c < 16; ++c) {
        u1[c] = b1s[c] + px * w1u[c] + py * w1u[16 + c] + pz * w1u[32 + c];
        v1s[t * 17 + c] = px * w1v[c] + py * w1v[16 + c] + pz * w1v[32 + c];
    }
    __syncthreads();

    // merge two sorted 20-lists -> set of 20 smallest
    unsigned ji[KN];
#pragma unroll
    for (int i = 0; i < KN; ++i)
        ji[i] = __float_as_uint(fminf(kA[i], kB[KN - 1 - i])) & 127u;
    unsigned* oi = g_idx1 + ((size_t)b * PP + t) * 5;
#pragma unroll
    for (int w = 0; w < 5; ++w)
        oi[w] = ji[4 * w] | (ji[4 * w + 1] << 8) | (ji[4 * w + 2] << 16) | (ji[4 * w + 3] << 24);

    float s[16], q[16];
#pragma unroll
    for (int c = 0; c < 16; ++c) { s[c] = 0.f; q[c] = 0.f; }
#pragma unroll
    for (int k = 0; k < KN; ++k) {
        int j = (int)ji[k];
#pragma unroll
        for (int c = 0; c < 16; ++c) {
            float h = u1[c] + v1s[j * 17 + c];
            s[c] += h; q[c] = fmaf(h, h, q[c]);
        }
    }
#pragma unroll
    for (int c = 0; c < 16; ++c) {
        for (int o = 16; o > 0; o >>= 1) {
            s[c] += __shfl_xor_sync(0xffffffffu, s[c], o);
            q[c] += __shfl_xor_sync(0xffffffffu, q[c], o);
        }
    }
    int lane = t & 31, wid = t >> 5;
    if (lane == 0) {
#pragma unroll
        for (int c = 0; c < 16; ++c) { wpart[wid][c] = s[c]; wpart[wid][16 + c] = q[c]; }
    }
    __syncthreads();
    if (t < 32) {
        float v = wpart[0][t] + wpart[1][t] + wpart[2][t] + wpart[3][t];
        atomicAdd(&g_stats[t], v);
    }
}

// ------------------------------------------------------------------
// K2: h1 = relu(bn1(u+vj)); packed stats of h1@W2+b2
__global__ __launch_bounds__(128) void k2_stats2(
    const float* __restrict__ pos,
    const float* __restrict__ w1, const float* __restrict__ b1,
    const float* __restrict__ g1, const float* __restrict__ be1,
    const float* __restrict__ w2, const float* __restrict__ b2)
{
    __shared__ float v1s[PP * 17];
    __shared__ float w1u[48], w1v[48], b1s[16];
    __shared__ __align__(16) float sw2[256];
    __shared__ __align__(16) float sb2[16];
    __shared__ float bn1s[16], bn1o[16];
    __shared__ float wpart[4][32];

    int b = blockIdx.x, t = threadIdx.x;
    float px = pos[(b * PP + t) * 3 + 0];
    float py = pos[(b * PP + t) * 3 + 1];
    float pz = pos[(b * PP + t) * 3 + 2];
    if (t < 48) { w1u[t] = w1[t] - w1[t + 48]; w1v[t] = w1[t + 48]; }
    if (t < 16) b1s[t] = b1[t];
    sw2[t] = w2[t]; sw2[t + 128] = w2[t + 128];
    if (t < 16) sb2[t] = b2[t];
    if (t >= 32 && t < 48) {
        int c = t - 32;
        const float N = (float)BG * PP * KN;
        float m = g_stats[c] / N;
        float v = g_stats[16 + c] / N - m * m;
        float sc = g1[c] * rsqrtf(v + EPSB);
        bn1s[c] = sc; bn1o[c] = be1[c] - m * sc;
    }
    __syncthreads();

    float u1[16];
#pragma unroll
    for (int c = 0; c < 16; ++c) {
        u1[c] = b1s[c] + px * w1u[c] + py * w1u[16 + c] + pz * w1u[32 + c];
        v1s[t * 17 + c] = px * w1v[c] + py * w1v[16 + c] + pz * w1v[32 + c];
    }
    __syncthreads();

    const unsigned* oi = g_idx1 + ((size_t)b * PP + t) * 5;
    const ulonglong2* sw2u2 = (const ulonglong2*)sw2;
    const u64* sb2u = (const u64*)sb2;

    u64 S[8], Q[8];
#pragma unroll
    for (int g = 0; g < 8; ++g) { S[g] = 0ull; Q[g] = 0ull; }
#pragma unroll 1
    for (int w = 0; w < 5; ++w) {
        unsigned pk = oi[w];
#pragma unroll 1
        for (int kk = 0; kk < 4; ++kk) {
            int j = (int)(pk & 255u); pk >>= 8;
            float h1[16];
#pragma unroll
            for (int c = 0; c < 16; ++c) {
                float pre = u1[c] + v1s[j * 17 + c];
                h1[c] = fmaxf(fmaf(pre, bn1s[c], bn1o[c]), 0.f);
            }
            u64 A2[8];
#pragma unroll
            for (int g = 0; g < 8; ++g) A2[g] = sb2u[g];
#pragma unroll
            for (int f = 0; f < 16; ++f) {
                u64 hv = pk2(h1[f], h1[f]);
                ulonglong2 w0 = sw2u2[f * 4 + 0], w1q = sw2u2[f * 4 + 1];
                ulonglong2 w2q = sw2u2[f * 4 + 2], w3q = sw2u2[f * 4 + 3];
                A2[0] = fma2(hv, w0.x, A2[0]);  A2[1] = fma2(hv, w0.y, A2[1]);
                A2[2] = fma2(hv, w1q.x, A2[2]); A2[3] = fma2(hv, w1q.y, A2[3]);
                A2[4] = fma2(hv, w2q.x, A2[4]); A2[5] = fma2(hv, w2q.y, A2[5]);
                A2[6] = fma2(hv, w3q.x, A2[6]); A2[7] = fma2(hv, w3q.y, A2[7]);
            }
#pragma unroll
            for (int g = 0; g < 8; ++g) {
                S[g] = add2(S[g], A2[g]);
                Q[g] = fma2(A2[g], A2[g], Q[g]);
            }
        }
    }
    float s[16], q[16];
#pragma unroll
    for (int g = 0; g < 8; ++g) {
        upk2(s[2 * g], s[2 * g + 1], S[g]);
        upk2(q[2 * g], q[2 * g + 1], Q[g]);
    }
#pragma unroll
    for (int c = 0; c < 16; ++c) {
        for (int o = 16; o > 0; o >>= 1) {
            s[c] += __shfl_xor_sync(0xffffffffu, s[c], o);
            q[c] += __shfl_xor_sync(0xffffffffu, q[c], o);
        }
    }
    int lane = t & 31, wid = t >> 5;
    if (lane == 0) {
#pragma unroll
        for (int c = 0; c < 16; ++c) { wpart[wid][c] = s[c]; wpart[wid][16 + c] = q[c]; }
    }
    __syncthreads();
    if (t < 32) {
        float v = wpart[0][t] + wpart[1][t] + wpart[2][t] + wpart[3][t];
        atomicAdd(&g_stats[32 + t], v);
    }
}

// ------------------------------------------------------------------
// K3: conv1 (explicit edge-pairs, shared weight loads) -> x1 ; kNN2 ;
//     conv2 ; lin1 (unroll 4) ; head ; log_softmax
__global__ __launch_bounds__(128, 1) void k3_mega(
    const float* __restrict__ pos,
    const float* __restrict__ w1, const float* __restrict__ b1,
    const float* __restrict__ g1, const float* __restrict__ be1,
    const float* __restrict__ w2, const float* __restrict__ b2,
    const float* __restrict__ g2, const float* __restrict__ be2,
    const float* __restrict__ w3, const float* __restrict__ b3,
    const float* __restrict__ c2w, const float* __restrict__ c2b,
    const float* __restrict__ lw,  const float* __restrict__ lb,
    const float* __restrict__ mw1, const float* __restrict__ mb1,
    const float* __restrict__ mw2, const float* __restrict__ mb2,
    const float* __restrict__ mw3, const float* __restrict__ mb3,
    float* __restrict__ out)
{
    __shared__ __align__(16) float pool[6784];
    __shared__ float sn2[PP];
    __shared__ unsigned char nb2[PP * KN];
    __shared__ float w1u[48], w1v[48], b1s[16], bn1s[16], bn1o[16];
    __shared__ __align__(16) float sw2[256];
    __shared__ __align__(16) float sw3[256];
    __shared__ __align__(16) float sb2[16];
    __shared__ float sb3[16], bn2s[16], bn2o[16];
    __shared__ __align__(16) float c2u[512];
    __shared__ __align__(16) float c2v[512];
    __shared__ __align__(16) float c2bs[32];
    __shared__ float wm[128 * 4];
    __shared__ float gvec[128], h1s[64], h2s[64], outs[2];

    int b = blockIdx.x, t = threadIdx.x;
    int lane = t & 31, wid = t >> 5;
    float px = pos[(b * PP + t) * 3 + 0];
    float py = pos[(b * PP + t) * 3 + 1];
    float pz = pos[(b * PP + t) * 3 + 2];
    if (t < 48) { w1u[t] = w1[t] - w1[t + 48]; w1v[t] = w1[t + 48]; }
    if (t < 16) { b1s[t] = b1[t]; sb2[t] = b2[t]; sb3[t] = b3[t]; }
    sw2[t] = w2[t]; sw2[t + 128] = w2[t + 128];
    sw3[t] = w3[t]; sw3[t + 128] = w3[t + 128];
#pragma unroll
    for (int i = t; i < 512; i += 128) { c2u[i] = c2w[i] - c2w[i + 512]; c2v[i] = c2w[i + 512]; }
    if (t < 32) c2bs[t] = c2b[t];
    {
        const float N = (float)BG * PP * KN;
        if (t >= 64 && t < 80) {
            int c = t - 64;
            float m = g_stats[c] / N;
            float v = g_stats[16 + c] / N - m * m;
            float sc = g1[c] * rsqrtf(v + EPSB);
            bn1s[c] = sc; bn1o[c] = be1[c] - m * sc;
        } else if (t >= 80 && t < 96) {
            int c = t - 80;
            float m = g_stats[32 + c] / N;
            float v = g_stats[48 + c] / N - m * m;
            float sc = g2[c] * rsqrtf(v + EPSB);
            bn2s[c] = sc; bn2o[c] = be2[c] - m * sc;
        }
    }
    __syncthreads();   // all weights/bn consts ready; pool free

    // phase A: u1 (regs) + v1 rows (pool, stride 20, float4 writes)
    float u1[16];
    {
        float vv[16];
#pragma unroll
        for (int c = 0; c < 16; ++c) {
            u1[c] = b1s[c] + px * w1u[c] + py * w1u[16 + c] + pz * w1u[32 + c];
            vv[c] = px * w1v[c] + py * w1v[16 + c] + pz * w1v[32 + c];
        }
        float4* vr = (float4*)pool + t * 5;
#pragma unroll
        for (int g = 0; g < 4; ++g)
            vr[g] = make_float4(vv[4 * g], vv[4 * g + 1], vv[4 * g + 2], vv[4 * g + 3]);
    }
    __syncthreads();

    // ---- conv1 over 20 edges: EXPLICIT PAIRS, weights loaded once per pair ----
    const unsigned* oi = g_idx1 + ((size_t)b * PP + t) * 5;
    const ulonglong2* sw2u2 = (const ulonglong2*)sw2;
    const ulonglong2* sw3u2 = (const ulonglong2*)sw3;
    const u64* sb2u = (const u64*)sb2;
    float x1a[16];
#pragma unroll
    for (int c = 0; c < 16; ++c) x1a[c] = -1e30f;
#pragma unroll 1
    for (int w = 0; w < 5; ++w) {
        unsigned pk = oi[w];
#pragma unroll 1
        for (int hp = 0; hp < 2; ++hp) {
            int j0 = (int)(pk & 255u); pk >>= 8;
            int j1 = (int)(pk & 255u); pk >>= 8;
            const float4* vpa = (const float4*)pool + j0 * 5;
            const float4* vpb = (const float4*)pool + j1 * 5;
            float4 qa0 = vpa[0], qa1 = vpa[1], qa2 = vpa[2], qa3 = vpa[3];
            float4 qb0 = vpb[0], qb1 = vpb[1], qb2 = vpb[2], qb3 = vpb[3];
            float hA[16], hB[16];
            hA[0]  = fmaxf(fmaf(u1[0]  + qa0.x, bn1s[0],  bn1o[0]),  0.f);
            hA[1]  = fmaxf(fmaf(u1[1]  + qa0.y, bn1s[1],  bn1o[1]),  0.f);
            hA[2]  = fmaxf(fmaf(u1[2]  + qa0.z, bn1s[2],  bn1o[2]),  0.f);
            hA[3]  = fmaxf(fmaf(u1[3]  + qa0.w, bn1s[3],  bn1o[3]),  0.f);
            hA[4]  = fmaxf(fmaf(u1[4]  + qa1.x, bn1s[4],  bn1o[4]),  0.f);
            hA[5]  = fmaxf(fmaf(u1[5]  + qa1.y, bn1s[5],  bn1o[5]),  0.f);
            hA[6]  = fmaxf(fmaf(u1[6]  + qa1.z, bn1s[6],  bn1o[6]),  0.f);
            hA[7]  = fmaxf(fmaf(u1[7]  + qa1.w, bn1s[7],  bn1o[7]),  0.f);
            hA[8]  = fmaxf(fmaf(u1[8]  + qa2.x, bn1s[8],  bn1o[8]),  0.f);
            hA[9]  = fmaxf(fmaf(u1[9]  + qa2.y, bn1s[9],  bn1o[9]),  0.f);
            hA[10] = fmaxf(fmaf(u1[10] + qa2.z, bn1s[10], bn1o[10]), 0.f);
            hA[11] = fmaxf(fmaf(u1[11] + qa2.w, bn1s[11], bn1o[11]), 0.f);
            hA[12] = fmaxf(fmaf(u1[12] + qa3.x, bn1s[12], bn1o[12]), 0.f);
            hA[13] = fmaxf(fmaf(u1[13] + qa3.y, bn1s[13], bn1o[13]), 0.f);
            hA[14] = fmaxf(fmaf(u1[14] + qa3.z, bn1s[14], bn1o[14]), 0.f);
            hA[15] = fmaxf(fmaf(u1[15] + qa3.w, bn1s[15], bn1o[15]), 0.f);
            hB[0]  = fmaxf(fmaf(u1[0]  + qb0.x, bn1s[0],  bn1o[0]),  0.f);
            hB[1]  = fmaxf(fmaf(u1[1]  + qb0.y, bn1s[1],  bn1o[1]),  0.f);
            hB[2]  = fmaxf(fmaf(u1[2]  + qb0.z, bn1s[2],  bn1o[2]),  0.f);
            hB[3]  = fmaxf(fmaf(u1[3]  + qb0.w, bn1s[3],  bn1o[3]),  0.f);
            hB[4]  = fmaxf(fmaf(u1[4]  + qb1.x, bn1s[4],  bn1o[4]),  0.f);
            hB[5]  = fmaxf(fmaf(u1[5]  + qb1.y, bn1s[5],  bn1o[5]),  0.f);
            hB[6]  = fmaxf(fmaf(u1[6]  + qb1.z, bn1s[6],  bn1o[6]),  0.f);
            hB[7]  = fmaxf(fmaf(u1[7]  + qb1.w, bn1s[7],  bn1o[7]),  0.f);
            hB[8]  = fmaxf(fmaf(u1[8]  + qb2.x, bn1s[8],  bn1o[8]),  0.f);
            hB[9]  = fmaxf(fmaf(u1[9]  + qb2.y, bn1s[9],  bn1o[9]),  0.f);
            hB[10] = fmaxf(fmaf(u1[10] + qb2.z, bn1s[10], bn1o[10]), 0.f);
            hB[11] = fmaxf(fmaf(u1[11] + qb2.w, bn1s[11], bn1o[11]), 0.f);
            hB[12] = fmaxf(fmaf(u1[12] + qb3.x, bn1s[12], bn1o[12]), 0.f);
            hB[13] = fmaxf(fmaf(u1[13] + qb3.y, bn1s[13], bn1o[13]), 0.f);
            hB[14] = fmaxf(fmaf(u1[14] + qb3.z, bn1s[14], bn1o[14]), 0.f);
            hB[15] = fmaxf(fmaf(u1[15] + qb3.w, bn1s[15], bn1o[15]), 0.f);

            u64 A2a[8], A2b[8];
#pragma unroll
            for (int g = 0; g < 8; ++g) { A2a[g] = sb2u[g]; A2b[g] = sb2u[g]; }
#pragma unroll
            for (int f = 0; f < 16; ++f) {
                u64 ha = pk2(hA[f], hA[f]);
                u64 hb = pk2(hB[f], hB[f]);
                ulonglong2 w0 = sw2u2[f * 4 + 0], w1q = sw2u2[f * 4 + 1];
                ulonglong2 w2q = sw2u2[f * 4 + 2], w3q = sw2u2[f * 4 + 3];
                A2a[0] = fma2(ha, w0.x, A2a[0]);  A2b[0] = fma2(hb, w0.x, A2b[0]);
                A2a[1] = fma2(ha, w0.y, A2a[1]);  A2b[1] = fma2(hb, w0.y, A2b[1]);
                A2a[2] = fma2(ha, w1q.x, A2a[2]); A2b[2] = fma2(hb, w1q.x, A2b[2]);
                A2a[3] = fma2(ha, w1q.y, A2a[3]); A2b[3] = fma2(hb, w1q.y, A2b[3]);
                A2a[4] = fma2(ha, w2q.x, A2a[4]); A2b[4] = fma2(hb, w2q.x, A2b[4]);
                A2a[5] = fma2(ha, w2q.y, A2a[5]); A2b[5] = fma2(hb, w2q.y, A2b[5]);
                A2a[6] = fma2(ha, w3q.x, A2a[6]); A2b[6] = fma2(hb, w3q.x, A2b[6]);
                A2a[7] = fma2(ha, w3q.y, A2a[7]); A2b[7] = fma2(hb, w3q.y, A2b[7]);
            }
#pragma unroll
            for (int g = 0; g < 8; ++g) {
                float a, bb; upk2(a, bb, A2a[g]);
                hA[2 * g]     = fmaxf(fmaf(a,  bn2s[2 * g],     bn2o[2 * g]),     0.f);
                hA[2 * g + 1] = fmaxf(fmaf(bb, bn2s[2 * g + 1], bn2o[2 * g + 1]), 0.f);
                float c, dd; upk2(c, dd, A2b[g]);
                hB[2 * g]     = fmaxf(fmaf(c,  bn2s[2 * g],     bn2o[2 * g]),     0.f);
                hB[2 * g + 1] = fmaxf(fmaf(dd, bn2s[2 * g + 1], bn2o[2 * g + 1]), 0.f);
            }
            u64 A3a[8], A3b[8];
#pragma unroll
            for (int g = 0; g < 8; ++g) { A3a[g] = 0ull; A3b[g] = 0ull; }
#pragma unroll
            for (int f = 0; f < 16; ++f) {
                u64 ha = pk2(hA[f], hA[f]);
                u64 hb = pk2(hB[f], hB[f]);
                ulonglong2 w0 = sw3u2[f * 4 + 0], w1q = sw3u2[f * 4 + 1];
                ulonglong2 w2q = sw3u2[f * 4 + 2], w3q = sw3u2[f * 4 + 3];
                A3a[0] = fma2(ha, w0.x, A3a[0]);  A3b[0] = fma2(hb, w0.x, A3b[0]);
                A3a[1] = fma2(ha, w0.y, A3a[1]);  A3b[1] = fma2(hb, w0.y, A3b[1]);
                A3a[2] = fma2(ha, w1q.x, A3a[2]); A3b[2] = fma2(hb, w1q.x, A3b[2]);
                A3a[3] = fma2(ha, w1q.y, A3a[3]); A3b[3] = fma2(hb, w1q.y, A3b[3]);
                A3a[4] = fma2(ha, w2q.x, A3a[4]); A3b[4] = fma2(hb, w2q.x, A3b[4]);
                A3a[5] = fma2(ha, w2q.y, A3a[5]); A3b[5] = fma2(hb, w2q.y, A3b[5]);
                A3a[6] = fma2(ha, w3q.x, A3a[6]); A3b[6] = fma2(hb, w3q.x, A3b[6]);
                A3a[7] = fma2(ha, w3q.y, A3a[7]); A3b[7] = fma2(hb, w3q.y, A3b[7]);
            }
#pragma unroll
            for (int g = 0; g < 8; ++g) {
                float a, bb; upk2(a, bb, A3a[g]);
                float c, dd; upk2(c, dd, A3b[g]);
                x1a[2 * g]     = fmaxf(x1a[2 * g],     fmaxf(a, c));
                x1a[2 * g + 1] = fmaxf(x1a[2 * g + 1], fmaxf(bb, dd));
            }
        }
    }
    float x1f[16];
    float n2 = 0.f;
#pragma unroll
    for (int c = 0; c < 16; ++c) { x1f[c] = x1a[c] + sb3[c]; n2 = fmaf(x1f[c], x1f[c], n2); }
    __syncthreads();   // all v1 reads done
    {
        float4* xr = (float4*)pool + t * 5;
#pragma unroll
        for (int g = 0; g < 4; ++g)
            xr[g] = make_float4(x1f[4 * g], x1f[4 * g + 1], x1f[4 * g + 2], x1f[4 * g + 3]);
        sn2[t] = n2;
    }
    __syncthreads();

    // ---- kNN2: 4 candidates/iter, packed f32x2 dots, 2 inserts per list ----
    u64 xq[8];
#pragma unroll
    for (int g = 0; g < 8; ++g) xq[g] = pk2(x1f[2 * g], x1f[2 * g + 1]);

    float kA[KN], kB[KN];
#pragma unroll
    for (int k = 0; k < KN; ++k) { kA[k] = 1e38f; kB[k] = 1e38f; }
#pragma unroll 1
    for (int j = 0; j < PP; j += 4) {
        float dd[4];
#pragma unroll
        for (int s = 0; s < 4; ++s) {
            const ulonglong2* rp = (const ulonglong2*)(pool + (j + s) * 20);
            ulonglong2 r0 = rp[0], r1 = rp[1], r2 = rp[2], r3 = rp[3];
            u64 a0 = 0ull, a1 = 0ull;
            a0 = fma2(xq[0], r0.x, a0); a1 = fma2(xq[1], r0.y, a1);
            a0 = fma2(xq[2], r1.x, a0); a1 = fma2(xq[3], r1.y, a1);
            a0 = fma2(xq[4], r2.x, a0); a1 = fma2(xq[5], r2.y, a1);
            a0 = fma2(xq[6], r3.x, a0); a1 = fma2(xq[7], r3.y, a1);
            float l0, h0, l1, h1; upk2(l0, h0, a0); upk2(l1, h1, a1);
            float dot = (l0 + h0) + (l1 + h1);
            dd[s] = n2 + sn2[j + s] - 2.f * dot;
        }
        if (j == t)     dd[0] = 1e30f;
        if (j + 1 == t) dd[1] = 1e30f;
        if (j + 2 == t) dd[2] = 1e30f;
        if (j + 3 == t) dd[3] = 1e30f;
        ins20(kA, embed(dd[0], j));
        ins20(kA, embed(dd[2], j + 2));
        ins20(kB, embed(dd[1], j + 1));
        ins20(kB, embed(dd[3], j + 3));
    }
#pragma unroll
    for (int k = 0; k < KN; ++k)
        nb2[t * KN + k] = (unsigned char)(__float_as_uint(fminf(kA[k], kB[KN - 1 - k])) & 127u);

    // ---- conv2: v2 = x1f@Wv -> smem (stride 33); x2 = u2 + max_k v2[j] ----
    float* v2s = pool + 2560;
    {
        const ulonglong2* cv = (const ulonglong2*)c2v;
        u64 V[16];
#pragma unroll
        for (int g = 0; g < 16; ++g) V[g] = 0ull;
#pragma unroll
        for (int f = 0; f < 16; ++f) {
            u64 hv = pk2(x1f[f], x1f[f]);
#pragma unroll
            for (int g = 0; g < 8; ++g) {
                ulonglong2 wv = cv[f * 8 + g];
                V[2 * g]     = fma2(hv, wv.x, V[2 * g]);
                V[2 * g + 1] = fma2(hv, wv.y, V[2 * g + 1]);
            }
        }
#pragma unroll
        for (int g = 0; g < 16; ++g) {
            float a, bb; upk2(a, bb, V[g]);
            v2s[t * 33 + 2 * g] = a; v2s[t * 33 + 2 * g + 1] = bb;
        }
    }
    __syncthreads();

    float x2m[32];
#pragma unroll
    for (int c = 0; c < 32; ++c) x2m[c] = -1e30f;
#pragma unroll 1
    for (int k = 0; k < KN; ++k) {
        int j = (int)nb2[t * KN + k];
#pragma unroll
        for (int c = 0; c < 32; ++c) x2m[c] = fmaxf(x2m[c], v2s[j * 33 + c]);
    }
    float x2a[32];
    {
        const ulonglong2* cu = (const ulonglong2*)c2u;
        const u64* cbu = (const u64*)c2bs;
        u64 U[16];
#pragma unroll
        for (int g = 0; g < 16; ++g) U[g] = cbu[g];
#pragma unroll
        for (int f = 0; f < 16; ++f) {
            u64 hv = pk2(x1f[f], x1f[f]);
#pragma unroll
            for (int g = 0; g < 8; ++g) {
                ulonglong2 wv = cu[f * 8 + g];
                U[2 * g]     = fma2(hv, wv.x, U[2 * g]);
                U[2 * g + 1] = fma2(hv, wv.y, U[2 * g + 1]);
            }
        }
#pragma unroll
        for (int g = 0; g < 16; ++g) {
            float a, bb; upk2(a, bb, U[g]);
            x2a[2 * g]     = a  + x2m[2 * g];
            x2a[2 * g + 1] = bb + x2m[2 * g + 1];
        }
    }
    __syncthreads();   // all v2/x1s reads done; pool free

    // ---- load lin1 weights transposed: lwt[c][f] = lw[f][c] (pool 0..6144) ----
#pragma unroll 1
    for (int i = t; i < 48 * 128; i += 128) {
        int c = i / 48, f = i - c * 48;
        pool[i] = lw[f * 128 + c];
    }
    __syncthreads();

    // ---- lin1: per-channel broadcast dot (packed) + shuffle/cross-warp max,
    //      4 channels in flight ----
    u64 F2[24];
#pragma unroll
    for (int g = 0; g < 8; ++g)  F2[g]     = pk2(x1f[2 * g], x1f[2 * g + 1]);
#pragma unroll
    for (int g = 0; g < 16; ++g) F2[8 + g] = pk2(x2a[2 * g], x2a[2 * g + 1]);
#pragma unroll 4
    for (int c = 0; c < 128; ++c) {
        const ulonglong2* rw = (const ulonglong2*)(pool + c * 48);
        u64 a0 = 0ull, a1 = 0ull;
#pragma unroll
        for (int g = 0; g < 12; ++g) {
            ulonglong2 wv = rw[g];
            a0 = fma2(F2[2 * g],     wv.x, a0);
            a1 = fma2(F2[2 * g + 1], wv.y, a1);
        }
        float lo, hi; upk2(lo, hi, add2(a0, a1));
        float v = lo + hi;
#pragma unroll
        for (int o = 16; o > 0; o >>= 1)
            v = fmaxf(v, __shfl_xor_sync(0xffffffffu, v, o));
        if (lane == 0) wm[c * 4 + wid] = v;
    }
    __syncthreads();
    gvec[t] = fmaxf(fmaxf(wm[t * 4 + 0], wm[t * 4 + 1]),
                    fmaxf(wm[t * 4 + 2], wm[t * 4 + 3])) + __ldg(lb + t);
    __syncthreads();

    // ---- head MLP 128->64->64->2 + log_softmax ----
    if (t < 64) {
        float a = mb1[t];
#pragma unroll 4
        for (int i = 0; i < 128; ++i) a = fmaf(gvec[i], mw1[i * 64 + t], a);
        h1s[t] = fmaxf(a, 0.f);
    }
    __syncthreads();
    if (t < 64) {
        float a = mb2[t];
#pragma unroll 4
        for (int i = 0; i < 64; ++i) a = fmaf(h1s[i], mw2[i * 64 + t], a);
        h2s[t] = fmaxf(a, 0.f);
    }
    __syncthreads();
    if (t < 2) {
        float a = mb3[t];
#pragma unroll 4
        for (int i = 0; i < 64; ++i) a = fmaf(h2s[i], mw3[i * 2 + t], a);
        outs[t] = a;
    }
    __syncthreads();
    if (t == 0) {
        float o0 = outs[0], o1 = outs[1];
        float m = fmaxf(o0, o1);
        float lse = m + logf(expf(o0 - m) + expf(o1 - m));
        out[b * 2 + 0] = o0 - lse;
        out[b * 2 + 1] = o1 - lse;
    }
}

// ------------------------------------------------------------------
extern "C" void kernel_launch(void* const* d_in, const int* in_sizes, int n_in,
                              void* d_out, int out_size)
{
    (void)in_sizes; (void)n_in; (void)out_size;
    const float* pos   = (const float*)d_in[0];
    const float* c1_w1 = (const float*)d_in[2];
    const float* c1_b1 = (const float*)d_in[3];
    const float* c1_g1 = (const float*)d_in[4];
    const float* c1_be1= (const float*)d_in[5];
    const float* c1_w2 = (const float*)d_in[6];
    const float* c1_b2 = (const float*)d_in[7];
    const float* c1_g2 = (const float*)d_in[8];
    const float* c1_be2= (const float*)d_in[9];
    const float* c1_w3 = (const float*)d_in[10];
    const float* c1_b3 = (const float*)d_in[11];
    const float* c2_w  = (const float*)d_in[12];
    const float* c2_b  = (const float*)d_in[13];
    const float* lw    = (const float*)d_in[14];
    const float* lb    = (const float*)d_in[15];
    const float* m_w1  = (const float*)d_in[16];
    const float* m_b1  = (const float*)d_in[17];
    const float* m_w2  = (const float*)d_in[18];
    const float* m_b2  = (const float*)d_in[19];
    const float* m_w3  = (const float*)d_in[20];
    const float* m_b3  = (const float*)d_in[21];
    float* out = (float*)d_out;

    k0_zero<<<1, 64>>>();
    k1_knn_stats<<<BG, 128>>>(pos, c1_w1, c1_b1);
    k2_stats2<<<BG, 128>>>(pos, c1_w1, c1_b1, c1_g1, c1_be1, c1_w2, c1_b2);
    k3_mega<<<BG, 128>>>(pos,
                         c1_w1, c1_b1, c1_g1, c1_be1,
                         c1_w2, c1_b2, c1_g2, c1_be2,
                         c1_w3, c1_b3,
                         c2_w, c2_b, lw, lb,
                         m_w1, m_b1, m_w2, m_b2, m_w3, m_b3,
                         out);
}

// round 13
// speedup vs baseline: 1.0199x; 1.0199x over previous
#include <cuda_runtime.h>
#include <math.h>

#define BG 1024
#define PP 128
#define KN 20
#define EPSB 1e-5f

typedef unsigned long long u64;

// ---- persistent scratch ----
__device__ unsigned int g_idx1[BG * PP * 5];   // 20 packed neighbor bytes per point
__device__ float g_stats[64];                  // sum1/sq1/sum2/sq2

__global__ void k0_zero() { if (threadIdx.x < 64) g_stats[threadIdx.x] = 0.f; }

__device__ __forceinline__ float embed(float d2, int j) {
    return __uint_as_float((__float_as_uint(d2) & 0xFFFFFF80u) | (unsigned)j);
}
__device__ __forceinline__ u64 pk2(float a, float b) {
    u64 r; asm("mov.b64 %0,{%1,%2};" : "=l"(r) : "f"(a), "f"(b)); return r;
}
__device__ __forceinline__ void upk2(float& a, float& b, u64 v) {
    asm("mov.b64 {%0,%1},%2;" : "=f"(a), "=f"(b) : "l"(v));
}
__device__ __forceinline__ u64 fma2(u64 a, u64 b, u64 c) {
    u64 d; asm("fma.rn.f32x2 %0,%1,%2,%3;" : "=l"(d) : "l"(a), "l"(b), "l"(c)); return d;
}
__device__ __forceinline__ u64 add2(u64 a, u64 b) {
    u64 d; asm("add.rn.f32x2 %0,%1,%2;" : "=l"(d) : "l"(a), "l"(b)); return d;
}
__device__ __forceinline__ void ins20(float (&kd)[KN], float dv) {
    kd[KN - 1] = fminf(kd[KN - 1], dv);
#pragma unroll
    for (int p = KN - 1; p > 0; --p) {
        float lo = fminf(kd[p - 1], kd[p]);
        float hi = fmaxf(kd[p - 1], kd[p]);
        kd[p - 1] = lo; kd[p] = hi;
    }
}

// ------------------------------------------------------------------
// K1: kNN on pos (2 lists, 4 candidates/iter) + BN1 stats  (unchanged)
__global__ __launch_bounds__(128) void k1_knn_stats(
    const float* __restrict__ pos,
    const float* __restrict__ w1, const float* __restrict__ b1)
{
    __shared__ float spx[PP], spy[PP], spz[PP], sn[PP];
    __shared__ float v1s[PP * 17];
    __shared__ float w1u[48], w1v[48], b1s[16];
    __shared__ float wpart[4][32];

    int b = blockIdx.x, t = threadIdx.x;
    float px = pos[(b * PP + t) * 3 + 0];
    float py = pos[(b * PP + t) * 3 + 1];
    float pz = pos[(b * PP + t) * 3 + 2];
    spx[t] = px; spy[t] = py; spz[t] = pz;
    if (t < 48) { w1u[t] = w1[t] - w1[t + 48]; w1v[t] = w1[t + 48]; }
    if (t < 16) b1s[t] = b1[t];
    float ni = px * px + py * py + pz * pz;
    sn[t] = ni;
    __syncthreads();

    float kA[KN], kB[KN];
#pragma unroll
    for (int k = 0; k < KN; ++k) { kA[k] = 1e38f; kB[k] = 1e38f; }
#pragma unroll 1
    for (int j = 0; j < PP; j += 4) {
        float d0 = ni + sn[j]     - 2.f * (px * spx[j]     + py * spy[j]     + pz * spz[j]);
        float d1 = ni + sn[j + 1] - 2.f * (px * spx[j + 1] + py * spy[j + 1] + pz * spz[j + 1]);
        float d2 = ni + sn[j + 2] - 2.f * (px * spx[j + 2] + py * spy[j + 2] + pz * spz[j + 2]);
        float d3 = ni + sn[j + 3] - 2.f * (px * spx[j + 3] + py * spy[j + 3] + pz * spz[j + 3]);
        if (j == t)     d0 = 1e30f;
        if (j + 1 == t) d1 = 1e30f;
        if (j + 2 == t) d2 = 1e30f;
        if (j + 3 == t) d3 = 1e30f;
        ins20(kA, embed(d0, j));
        ins20(kA, embed(d2, j + 2));
        ins20(kB, embed(d1, j + 1));
        ins20(kB, embed(d3, j + 3));
    }

    float u1[16];
#pragma unroll
    for (int c = 0; c < 16; ++c) {
        u1[c] = b1s[c] + px * w1u[c] + py * w1u[16 + c] + pz * w1u[32 + c];
        v1s[t * 17 + c] = px * w1v[c] + py * w1v[16 + c] + pz * w1v[32 + c];
    }
    __syncthreads();

    unsigned ji[KN];
#pragma unroll
    for (int i = 0; i < KN; ++i)
        ji[i] = __float_as_uint(fminf(kA[i], kB[KN - 1 - i])) & 127u;
    unsigned* oi = g_idx1 + ((size_t)b * PP + t) * 5;
#pragma unroll
    for (int w = 0; w < 5; ++w)
        oi[w] = ji[4 * w] | (ji[4 * w + 1] << 8) | (ji[4 * w + 2] << 16) | (ji[4 * w + 3] << 24);

    float s[16], q[16];
#pragma unroll
    for (int c = 0; c < 16; ++c) { s[c] = 0.f; q[c] = 0.f; }
#pragma unroll
    for (int k = 0; k < KN; ++k) {
        int j = (int)ji[k];
#pragma unroll
        for (int c = 0; c < 16; ++c) {
            float h = u1[c] + v1s[j * 17 + c];
            s[c] += h; q[c] = fmaf(h, h, q[c]);
        }
    }
#pragma unroll
    for (int c = 0; c < 16; ++c) {
        for (int o = 16; o > 0; o >>= 1) {
            s[c] += __shfl_xor_sync(0xffffffffu, s[c], o);
            q[c] += __shfl_xor_sync(0xffffffffu, q[c], o);
        }
    }
    int lane = t & 31, wid = t >> 5;
    if (lane == 0) {
#pragma unroll
        for (int c = 0; c < 16; ++c) { wpart[wid][c] = s[c]; wpart[wid][16 + c] = q[c]; }
    }
    __syncthreads();
    if (t < 32) {
        float v = wpart[0][t] + wpart[1][t] + wpart[2][t] + wpart[3][t];
        atomicAdd(&g_stats[t], v);
    }
}

// ------------------------------------------------------------------
// K2: h1 = relu(bn1(u+vj)); packed stats of h1@W2+b2  (unchanged)
__global__ __launch_bounds__(128) void k2_stats2(
    const float* __restrict__ pos,
    const float* __restrict__ w1, const float* __restrict__ b1,
    const float* __restrict__ g1, const float* __restrict__ be1,
    const float* __restrict__ w2, const float* __restrict__ b2)
{
    __shared__ float v1s[PP * 17];
    __shared__ float w1u[48], w1v[48], b1s[16];
    __shared__ __align__(16) float sw2[256];
    __shared__ __align__(16) float sb2[16];
    __shared__ float bn1s[16], bn1o[16];
    __shared__ float wpart[4][32];

    int b = blockIdx.x, t = threadIdx.x;
    float px = pos[(b * PP + t) * 3 + 0];
    float py = pos[(b * PP + t) * 3 + 1];
    float pz = pos[(b * PP + t) * 3 + 2];
    if (t < 48) { w1u[t] = w1[t] - w1[t + 48]; w1v[t] = w1[t + 48]; }
    if (t < 16) b1s[t] = b1[t];
    sw2[t] = w2[t]; sw2[t + 128] = w2[t + 128];
    if (t < 16) sb2[t] = b2[t];
    if (t >= 32 && t < 48) {
        int c = t - 32;
        const float N = (float)BG * PP * KN;
        float m = g_stats[c] / N;
        float v = g_stats[16 + c] / N - m * m;
        float sc = g1[c] * rsqrtf(v + EPSB);
        bn1s[c] = sc; bn1o[c] = be1[c] - m * sc;
    }
    __syncthreads();

    float u1[16];
#pragma unroll
    for (int c = 0; c < 16; ++c) {
        u1[c] = b1s[c] + px * w1u[c] + py * w1u[16 + c] + pz * w1u[32 + c];
        v1s[t * 17 + c] = px * w1v[c] + py * w1v[16 + c] + pz * w1v[32 + c];
    }
    __syncthreads();

    const unsigned* oi = g_idx1 + ((size_t)b * PP + t) * 5;
    const ulonglong2* sw2u2 = (const ulonglong2*)sw2;
    const u64* sb2u = (const u64*)sb2;

    u64 S[8], Q[8];
#pragma unroll
    for (int g = 0; g < 8; ++g) { S[g] = 0ull; Q[g] = 0ull; }
#pragma unroll 1
    for (int w = 0; w < 5; ++w) {
        unsigned pk = oi[w];
#pragma unroll 1
        for (int kk = 0; kk < 4; ++kk) {
            int j = (int)(pk & 255u); pk >>= 8;
            float h1[16];
#pragma unroll
            for (int c = 0; c < 16; ++c) {
                float pre = u1[c] + v1s[j * 17 + c];
                h1[c] = fmaxf(fmaf(pre, bn1s[c], bn1o[c]), 0.f);
            }
            u64 A2[8];
#pragma unroll
            for (int g = 0; g < 8; ++g) A2[g] = sb2u[g];
#pragma unroll
            for (int f = 0; f < 16; ++f) {
                u64 hv = pk2(h1[f], h1[f]);
                ulonglong2 w0 = sw2u2[f * 4 + 0], w1q = sw2u2[f * 4 + 1];
                ulonglong2 w2q = sw2u2[f * 4 + 2], w3q = sw2u2[f * 4 + 3];
                A2[0] = fma2(hv, w0.x, A2[0]);  A2[1] = fma2(hv, w0.y, A2[1]);
                A2[2] = fma2(hv, w1q.x, A2[2]); A2[3] = fma2(hv, w1q.y, A2[3]);
                A2[4] = fma2(hv, w2q.x, A2[4]); A2[5] = fma2(hv, w2q.y, A2[5]);
                A2[6] = fma2(hv, w3q.x, A2[6]); A2[7] = fma2(hv, w3q.y, A2[7]);
            }
#pragma unroll
            for (int g = 0; g < 8; ++g) {
                S[g] = add2(S[g], A2[g]);
                Q[g] = fma2(A2[g], A2[g], Q[g]);
            }
        }
    }
    float s[16], q[16];
#pragma unroll
    for (int g = 0; g < 8; ++g) {
        upk2(s[2 * g], s[2 * g + 1], S[g]);
        upk2(q[2 * g], q[2 * g + 1], Q[g]);
    }
#pragma unroll
    for (int c = 0; c < 16; ++c) {
        for (int o = 16; o > 0; o >>= 1) {
            s[c] += __shfl_xor_sync(0xffffffffu, s[c], o);
            q[c] += __shfl_xor_sync(0xffffffffu, q[c], o);
        }
    }
    int lane = t & 31, wid = t >> 5;
    if (lane == 0) {
#pragma unroll
        for (int c = 0; c < 16; ++c) { wpart[wid][c] = s[c]; wpart[wid][16 + c] = q[c]; }
    }
    __syncthreads();
    if (t < 32) {
        float v = wpart[0][t] + wpart[1][t] + wpart[2][t] + wpart[3][t];
        atomicAdd(&g_stats[32 + t], v);
    }
}

// ------------------------------------------------------------------
// K3: 256 threads = 2 per point. Each half-thread does half the serial work;
//     pairs combine via shfl_xor(.,1).
__global__ __launch_bounds__(256, 1) void k3_mega(
    const float* __restrict__ pos,
    const float* __restrict__ w1, const float* __restrict__ b1,
    const float* __restrict__ g1, const float* __restrict__ be1,
    const float* __restrict__ w2, const float* __restrict__ b2,
    const float* __restrict__ g2, const float* __restrict__ be2,
    const float* __restrict__ w3, const float* __restrict__ b3,
    const float* __restrict__ c2w, const float* __restrict__ c2b,
    const float* __restrict__ lw,  const float* __restrict__ lb,
    const float* __restrict__ mw1, const float* __restrict__ mb1,
    const float* __restrict__ mw2, const float* __restrict__ mb2,
    const float* __restrict__ mw3, const float* __restrict__ mb3,
    float* __restrict__ out)
{
    __shared__ __align__(16) float pool[6784];
    __shared__ float sn2[PP];
    __shared__ unsigned char nb2[PP * KN];
    __shared__ float w1u[48], w1v[48], b1s[16], bn1s[16], bn1o[16];
    __shared__ __align__(16) float sw2[256];
    __shared__ __align__(16) float sw3[256];
    __shared__ __align__(16) float sb2[16];
    __shared__ float sb3[16], bn2s[16], bn2o[16];
    __shared__ __align__(16) float c2u[512];
    __shared__ __align__(16) float c2v[512];
    __shared__ __align__(16) float c2bs[32];
    __shared__ float wm[128 * 8];
    __shared__ float gvec[128], h1s[64], h2s[64], outs[2];

    int b = blockIdx.x, t = threadIdx.x;
    int p = t >> 1, h = t & 1;
    int lane = t & 31, wid = t >> 5;
    float px = pos[(b * PP + p) * 3 + 0];
    float py = pos[(b * PP + p) * 3 + 1];
    float pz = pos[(b * PP + p) * 3 + 2];
    if (t < 48) { w1u[t] = w1[t] - w1[t + 48]; w1v[t] = w1[t + 48]; }
    if (t < 16) { b1s[t] = b1[t]; sb2[t] = b2[t]; sb3[t] = b3[t]; }
    if (t < 256) { sw2[t] = w2[t]; sw3[t] = w3[t]; }
#pragma unroll
    for (int i = t; i < 512; i += 256) { c2u[i] = c2w[i] - c2w[i + 512]; c2v[i] = c2w[i + 512]; }
    if (t < 32) c2bs[t] = c2b[t];
    {
        const float N = (float)BG * PP * KN;
        if (t >= 64 && t < 80) {
            int c = t - 64;
            float m = g_stats[c] / N;
            float v = g_stats[16 + c] / N - m * m;
            float sc = g1[c] * rsqrtf(v + EPSB);
            bn1s[c] = sc; bn1o[c] = be1[c] - m * sc;
        } else if (t >= 80 && t < 96) {
            int c = t - 80;
            float m = g_stats[32 + c] / N;
            float v = g_stats[48 + c] / N - m * m;
            float sc = g2[c] * rsqrtf(v + EPSB);
            bn2s[c] = sc; bn2o[c] = be2[c] - m * sc;
        }
    }
    __syncthreads();

    // phase A: u1 (both halves) + v1 rows (h==0 writes)
    float u1[16];
    {
        float vv[16];
#pragma unroll
        for (int c = 0; c < 16; ++c) {
            u1[c] = b1s[c] + px * w1u[c] + py * w1u[16 + c] + pz * w1u[32 + c];
            vv[c] = px * w1v[c] + py * w1v[16 + c] + pz * w1v[32 + c];
        }
        if (h == 0) {
            float4* vr = (float4*)pool + p * 5;
#pragma unroll
            for (int g = 0; g < 4; ++g)
                vr[g] = make_float4(vv[4 * g], vv[4 * g + 1], vv[4 * g + 2], vv[4 * g + 3]);
        }
    }
    __syncthreads();

    // ---- conv1: each half does bytes {h, h+2} of each word = 10 edges ----
    const unsigned* oi = g_idx1 + ((size_t)b * PP + p) * 5;
    const ulonglong2* sw2u2 = (const ulonglong2*)sw2;
    const ulonglong2* sw3u2 = (const ulonglong2*)sw3;
    const u64* sb2u = (const u64*)sb2;
    float x1a[16];
#pragma unroll
    for (int c = 0; c < 16; ++c) x1a[c] = -1e30f;
#pragma unroll 1
    for (int w = 0; w < 5; ++w) {
        unsigned pk = oi[w];
#pragma unroll 1
        for (int e = 0; e < 2; ++e) {
            int j = (int)((pk >> (8 * (h + 2 * e))) & 255u);
            const float4* vp = (const float4*)pool + j * 5;
            float4 q0 = vp[0], q1 = vp[1], q2 = vp[2], q3 = vp[3];
            float h1v[16];
            h1v[0]  = fmaxf(fmaf(u1[0]  + q0.x, bn1s[0],  bn1o[0]),  0.f);
            h1v[1]  = fmaxf(fmaf(u1[1]  + q0.y, bn1s[1],  bn1o[1]),  0.f);
            h1v[2]  = fmaxf(fmaf(u1[2]  + q0.z, bn1s[2],  bn1o[2]),  0.f);
            h1v[3]  = fmaxf(fmaf(u1[3]  + q0.w, bn1s[3],  bn1o[3]),  0.f);
            h1v[4]  = fmaxf(fmaf(u1[4]  + q1.x, bn1s[4],  bn1o[4]),  0.f);
            h1v[5]  = fmaxf(fmaf(u1[5]  + q1.y, bn1s[5],  bn1o[5]),  0.f);
            h1v[6]  = fmaxf(fmaf(u1[6]  + q1.z, bn1s[6],  bn1o[6]),  0.f);
            h1v[7]  = fmaxf(fmaf(u1[7]  + q1.w, bn1s[7],  bn1o[7]),  0.f);
            h1v[8]  = fmaxf(fmaf(u1[8]  + q2.x, bn1s[8],  bn1o[8]),  0.f);
            h1v[9]  = fmaxf(fmaf(u1[9]  + q2.y, bn1s[9],  bn1o[9]),  0.f);
            h1v[10] = fmaxf(fmaf(u1[10] + q2.z, bn1s[10], bn1o[10]), 0.f);
            h1v[11] = fmaxf(fmaf(u1[11] + q2.w, bn1s[11], bn1o[11]), 0.f);
            h1v[12] = fmaxf(fmaf(u1[12] + q3.x, bn1s[12], bn1o[12]), 0.f);
            h1v[13] = fmaxf(fmaf(u1[13] + q3.y, bn1s[13], bn1o[13]), 0.f);
            h1v[14] = fmaxf(fmaf(u1[14] + q3.z, bn1s[14], bn1o[14]), 0.f);
            h1v[15] = fmaxf(fmaf(u1[15] + q3.w, bn1s[15], bn1o[15]), 0.f);

            u64 A2[8];
#pragma unroll
            for (int g = 0; g < 8; ++g) A2[g] = sb2u[g];
#pragma unroll
            for (int f = 0; f < 16; ++f) {
                u64 hv = pk2(h1v[f], h1v[f]);
                ulonglong2 w0 = sw2u2[f * 4 + 0], w1q = sw2u2[f * 4 + 1];
                ulonglong2 w2q = sw2u2[f * 4 + 2], w3q = sw2u2[f * 4 + 3];
                A2[0] = fma2(hv, w0.x, A2[0]);  A2[1] = fma2(hv, w0.y, A2[1]);
                A2[2] = fma2(hv, w1q.x, A2[2]); A2[3] = fma2(hv, w1q.y, A2[3]);
                A2[4] = fma2(hv, w2q.x, A2[4]); A2[5] = fma2(hv, w2q.y, A2[5]);
                A2[6] = fma2(hv, w3q.x, A2[6]); A2[7] = fma2(hv, w3q.y, A2[7]);
            }
            float h2v[16];
#pragma unroll
            for (int g = 0; g < 8; ++g) {
                float a, bb; upk2(a, bb, A2[g]);
                h2v[2 * g]     = fmaxf(fmaf(a,  bn2s[2 * g],     bn2o[2 * g]),     0.f);
                h2v[2 * g + 1] = fmaxf(fmaf(bb, bn2s[2 * g + 1], bn2o[2 * g + 1]), 0.f);
            }
            u64 A3[8];
#pragma unroll
            for (int g = 0; g < 8; ++g) A3[g] = 0ull;
#pragma unroll
            for (int f = 0; f < 16; ++f) {
                u64 hv = pk2(h2v[f], h2v[f]);
                ulonglong2 w0 = sw3u2[f * 4 + 0], w1q = sw3u2[f * 4 + 1];
                ulonglong2 w2q = sw3u2[f * 4 + 2], w3q = sw3u2[f * 4 + 3];
                A3[0] = fma2(hv, w0.x, A3[0]);  A3[1] = fma2(hv, w0.y, A3[1]);
                A3[2] = fma2(hv, w1q.x, A3[2]); A3[3] = fma2(hv, w1q.y, A3[3]);
                A3[4] = fma2(hv, w2q.x, A3[4]); A3[5] = fma2(hv, w2q.y, A3[5]);
                A3[6] = fma2(hv, w3q.x, A3[6]); A3[7] = fma2(hv, w3q.y, A3[7]);
            }
#pragma unroll
            for (int g = 0; g < 8; ++g) {
                float a, bb; upk2(a, bb, A3[g]);
                x1a[2 * g]     = fmaxf(x1a[2 * g],     a);
                x1a[2 * g + 1] = fmaxf(x1a[2 * g + 1], bb);
            }
        }
    }
    // pair combine (10+10 edges)
#pragma unroll
    for (int c = 0; c < 16; ++c)
        x1a[c] = fmaxf(x1a[c], __shfl_xor_sync(0xffffffffu, x1a[c], 1));
    float x1f[16];
    float n2 = 0.f;
#pragma unroll
    for (int c = 0; c < 16; ++c) { x1f[c] = x1a[c] + sb3[c]; n2 = fmaf(x1f[c], x1f[c], n2); }
    __syncthreads();   // all v1 reads done
    if (h == 0) {
        float4* xr = (float4*)pool + p * 5;
#pragma unroll
        for (int g = 0; g < 4; ++g)
            xr[g] = make_float4(x1f[4 * g], x1f[4 * g + 1], x1f[4 * g + 2], x1f[4 * g + 3]);
        sn2[p] = n2;
    }
    __syncthreads();

    // ---- kNN2: each half scans 64 candidates into ONE list; pair-merge ----
    u64 xq[8];
#pragma unroll
    for (int g = 0; g < 8; ++g) xq[g] = pk2(x1f[2 * g], x1f[2 * g + 1]);

    float kL[KN];
#pragma unroll
    for (int k = 0; k < KN; ++k) kL[k] = 1e38f;
    int jbase = h * 64;
#pragma unroll 1
    for (int jo = 0; jo < 64; jo += 4) {
        int j = jbase + jo;
        float dd[4];
#pragma unroll
        for (int s = 0; s < 4; ++s) {
            const ulonglong2* rp = (const ulonglong2*)(pool + (j + s) * 20);
            ulonglong2 r0 = rp[0], r1 = rp[1], r2 = rp[2], r3 = rp[3];
            u64 a0 = 0ull, a1 = 0ull;
            a0 = fma2(xq[0], r0.x, a0); a1 = fma2(xq[1], r0.y, a1);
            a0 = fma2(xq[2], r1.x, a0); a1 = fma2(xq[3], r1.y, a1);
            a0 = fma2(xq[4], r2.x, a0); a1 = fma2(xq[5], r2.y, a1);
            a0 = fma2(xq[6], r3.x, a0); a1 = fma2(xq[7], r3.y, a1);
            float l0, h0, l1, h1; upk2(l0, h0, a0); upk2(l1, h1, a1);
            float dot = (l0 + h0) + (l1 + h1);
            dd[s] = n2 + sn2[j + s] - 2.f * dot;
        }
        if (j == p)     dd[0] = 1e30f;
        if (j + 1 == p) dd[1] = 1e30f;
        if (j + 2 == p) dd[2] = 1e30f;
        if (j + 3 == p) dd[3] = 1e30f;
        ins20(kL, embed(dd[0], j));
        ins20(kL, embed(dd[1], j + 1));
        ins20(kL, embed(dd[2], j + 2));
        ins20(kL, embed(dd[3], j + 3));
    }
    // partner merge: top20(A ∪ B) = min(A[i], B[19-i])
    {
        float kP[KN];
#pragma unroll
        for (int k = 0; k < KN; ++k)
            kP[k] = __shfl_xor_sync(0xffffffffu, kL[k], 1);
        if (h == 0) {
#pragma unroll
            for (int k = 0; k < KN; ++k)
                nb2[p * KN + k] = (unsigned char)(__float_as_uint(fminf(kL[k], kP[KN - 1 - k])) & 127u);
        }
    }

    // ---- conv2: each half computes/writes 16 of 32 v2 channels ----
    float* v2s = pool + 2560;
    {
        const ulonglong2* cv = (const ulonglong2*)c2v;
        u64 V[8];
#pragma unroll
        for (int g = 0; g < 8; ++g) V[g] = 0ull;
#pragma unroll
        for (int f = 0; f < 16; ++f) {
            u64 hv = pk2(x1f[f], x1f[f]);
#pragma unroll
            for (int g = 0; g < 4; ++g) {
                ulonglong2 wv = cv[f * 8 + 4 * h + g];
                V[2 * g]     = fma2(hv, wv.x, V[2 * g]);
                V[2 * g + 1] = fma2(hv, wv.y, V[2 * g + 1]);
            }
        }
#pragma unroll
        for (int g = 0; g < 8; ++g) {
            float a, bb; upk2(a, bb, V[g]);
            v2s[p * 33 + 16 * h + 2 * g] = a;
            v2s[p * 33 + 16 * h + 2 * g + 1] = bb;
        }
    }
    __syncthreads();

    // x2m: each half gathers 10 neighbors (k = h, h+2, ...), then pair-max
    float x2m[32];
#pragma unroll
    for (int c = 0; c < 32; ++c) x2m[c] = -1e30f;
#pragma unroll 1
    for (int k = h; k < KN; k += 2) {
        int j = (int)nb2[p * KN + k];
#pragma unroll
        for (int c = 0; c < 32; ++c) x2m[c] = fmaxf(x2m[c], v2s[j * 33 + c]);
    }
#pragma unroll
    for (int c = 0; c < 32; ++c)
        x2m[c] = fmaxf(x2m[c], __shfl_xor_sync(0xffffffffu, x2m[c], 1));

    float x2a[32];
    {
        const ulonglong2* cu = (const ulonglong2*)c2u;
        const u64* cbu = (const u64*)c2bs;
        u64 U[16];
#pragma unroll
        for (int g = 0; g < 16; ++g) U[g] = cbu[g];
#pragma unroll
        for (int f = 0; f < 16; ++f) {
            u64 hv = pk2(x1f[f], x1f[f]);
#pragma unroll
            for (int g = 0; g < 8; ++g) {
                ulonglong2 wv = cu[f * 8 + g];
                U[2 * g]     = fma2(hv, wv.x, U[2 * g]);
                U[2 * g + 1] = fma2(hv, wv.y, U[2 * g + 1]);
            }
        }
#pragma unroll
        for (int g = 0; g < 16; ++g) {
            float a, bb; upk2(a, bb, U[g]);
            x2a[2 * g]     = a  + x2m[2 * g];
            x2a[2 * g + 1] = bb + x2m[2 * g + 1];
        }
    }
    __syncthreads();   // all v2/x1s reads done; pool free

    // ---- load lin1 weights transposed: lwt[c][f] = lw[f][c] ----
#pragma unroll 1
    for (int i = t; i < 48 * 128; i += 256) {
        int c = i / 48, f = i - c * 48;
        pool[i] = lw[f * 128 + c];
    }
    __syncthreads();

    // ---- lin1: thread handles 64 channels (c = 2i + h); parity shuffle max ----
    u64 F2[24];
#pragma unroll
    for (int g = 0; g < 8; ++g)  F2[g]     = pk2(x1f[2 * g], x1f[2 * g + 1]);
#pragma unroll
    for (int g = 0; g < 16; ++g) F2[8 + g] = pk2(x2a[2 * g], x2a[2 * g + 1]);
#pragma unroll 4
    for (int i = 0; i < 64; ++i) {
        int c = 2 * i + h;
        const ulonglong2* rw = (const ulonglong2*)(pool + c * 48);
        u64 a0 = 0ull, a1 = 0ull;
#pragma unroll
        for (int g = 0; g < 12; ++g) {
            ulonglong2 wv = rw[g];
            a0 = fma2(F2[2 * g],     wv.x, a0);
            a1 = fma2(F2[2 * g + 1], wv.y, a1);
        }
        float lo, hi; upk2(lo, hi, add2(a0, a1));
        float v = lo + hi;
        // reduce over the 16 same-parity lanes (16 points in this warp)
#pragma unroll
        for (int o = 2; o <= 16; o <<= 1)
            v = fmaxf(v, __shfl_xor_sync(0xffffffffu, v, o));
        if (lane < 2) wm[c * 8 + wid] = v;
    }
    __syncthreads();
    if (t < 128) {
        float v = wm[t * 8 + 0];
#pragma unroll
        for (int wsub = 1; wsub < 8; ++wsub) v = fmaxf(v, wm[t * 8 + wsub]);
        gvec[t] = v + __ldg(lb + t);
    }
    __syncthreads();

    // ---- head MLP 128->64->64->2 + log_softmax ----
    if (t < 64) {
        float a = mb1[t];
#pragma unroll 4
        for (int i = 0; i < 128; ++i) a = fmaf(gvec[i], mw1[i * 64 + t], a);
        h1s[t] = fmaxf(a, 0.f);
    }
    __syncthreads();
    if (t < 64) {
        float a = mb2[t];
#pragma unroll 4
        for (int i = 0; i < 64; ++i) a = fmaf(h1s[i], mw2[i * 64 + t], a);
        h2s[t] = fmaxf(a, 0.f);
    }
    __syncthreads();
    if (t < 2) {
        float a = mb3[t];
#pragma unroll 4
        for (int i = 0; i < 64; ++i) a = fmaf(h2s[i], mw3[i * 2 + t], a);
        outs[t] = a;
    }
    __syncthreads();
    if (t == 0) {
        float o0 = outs[0], o1 = outs[1];
        float m = fmaxf(o0, o1);
        float lse = m + logf(expf(o0 - m) + expf(o1 - m));
        out[b * 2 + 0] = o0 - lse;
        out[b * 2 + 1] = o1 - lse;
    }
}

// ------------------------------------------------------------------
extern "C" void kernel_launch(void* const* d_in, const int* in_sizes, int n_in,
                              void* d_out, int out_size)
{
    (void)in_sizes; (void)n_in; (void)out_size;
    const float* pos   = (const float*)d_in[0];
    const float* c1_w1 = (const float*)d_in[2];
    const float* c1_b1 = (const float*)d_in[3];
    const float* c1_g1 = (const float*)d_in[4];
    const float* c1_be1= (const float*)d_in[5];
    const float* c1_w2 = (const float*)d_in[6];
    const float* c1_b2 = (const float*)d_in[7];
    const float* c1_g2 = (const float*)d_in[8];
    const float* c1_be2= (const float*)d_in[9];
    const float* c1_w3 = (const float*)d_in[10];
    const float* c1_b3 = (const float*)d_in[11];
    const float* c2_w  = (const float*)d_in[12];
    const float* c2_b  = (const float*)d_in[13];
    const float* lw    = (const float*)d_in[14];
    const float* lb    = (const float*)d_in[15];
    const float* m_w1  = (const float*)d_in[16];
    const float* m_b1  = (const float*)d_in[17];
    const float* m_w2  = (const float*)d_in[18];
    const float* m_b2  = (const float*)d_in[19];
    const float* m_w3  = (const float*)d_in[20];
    const float* m_b3  = (const float*)d_in[21];
    float* out = (float*)d_out;

    k0_zero<<<1, 64>>>();
    k1_knn_stats<<<BG, 128>>>(pos, c1_w1, c1_b1);
    k2_stats2<<<BG, 128>>>(pos, c1_w1, c1_b1, c1_g1, c1_be1, c1_w2, c1_b2);
    k3_mega<<<BG, 256>>>(pos,
                         c1_w1, c1_b1, c1_g1, c1_be1,
                         c1_w2, c1_b2, c1_g2, c1_be2,
                         c1_w3, c1_b3,
                         c2_w, c2_b, lw, lb,
                         m_w1, m_b1, m_w2, m_b2, m_w3, m_b3,
                         out);
}

// round 14
// speedup vs baseline: 1.1075x; 1.0860x over previous
#include <cuda_runtime.h>
#include <math.h>

#define BG 1024
#define PP 128
#define KN 20
#define EPSB 1e-5f

typedef unsigned long long u64;

// ---- persistent scratch ----
__device__ unsigned int g_idx1[BG * PP * 5];   // 20 packed neighbor bytes per point
__device__ float g_stats[64];                  // sum1/sq1/sum2/sq2

__global__ void k0_zero() { if (threadIdx.x < 64) g_stats[threadIdx.x] = 0.f; }

__device__ __forceinline__ float embed(float d2, int j) {
    return __uint_as_float((__float_as_uint(d2) & 0xFFFFFF80u) | (unsigned)j);
}
__device__ __forceinline__ u64 pk2(float a, float b) {
    u64 r; asm("mov.b64 %0,{%1,%2};" : "=l"(r) : "f"(a), "f"(b)); return r;
}
__device__ __forceinline__ void upk2(float& a, float& b, u64 v) {
    asm("mov.b64 {%0,%1},%2;" : "=f"(a), "=f"(b) : "l"(v));
}
__device__ __forceinline__ u64 fma2(u64 a, u64 b, u64 c) {
    u64 d; asm("fma.rn.f32x2 %0,%1,%2,%3;" : "=l"(d) : "l"(a), "l"(b), "l"(c)); return d;
}
__device__ __forceinline__ u64 add2(u64 a, u64 b) {
    u64 d; asm("add.rn.f32x2 %0,%1,%2;" : "=l"(d) : "l"(a), "l"(b)); return d;
}
__device__ __forceinline__ void ins20(float (&kd)[KN], float dv) {
    kd[KN - 1] = fminf(kd[KN - 1], dv);
#pragma unroll
    for (int p = KN - 1; p > 0; --p) {
        float lo = fminf(kd[p - 1], kd[p]);
        float hi = fmaxf(kd[p - 1], kd[p]);
        kd[p - 1] = lo; kd[p] = hi;
    }
}

// ------------------------------------------------------------------
// K1: kNN on pos (2 lists, 4 cand/iter) + factored BN1 pre-activation stats
__global__ __launch_bounds__(128) void k1_knn_stats(
    const float* __restrict__ pos,
    const float* __restrict__ w1, const float* __restrict__ b1)
{
    __shared__ float spx[PP], spy[PP], spz[PP], sn[PP];
    __shared__ float v1s[PP * 17];
    __shared__ float w1u[48], w1v[48], b1s[16];
    __shared__ float wpart[4][32];

    int b = blockIdx.x, t = threadIdx.x;
    float px = pos[(b * PP + t) * 3 + 0];
    float py = pos[(b * PP + t) * 3 + 1];
    float pz = pos[(b * PP + t) * 3 + 2];
    spx[t] = px; spy[t] = py; spz[t] = pz;
    if (t < 48) { w1u[t] = w1[t] - w1[t + 48]; w1v[t] = w1[t + 48]; }
    if (t < 16) b1s[t] = b1[t];
    float ni = px * px + py * py + pz * pz;
    sn[t] = ni;
    __syncthreads();

    float kA[KN], kB[KN];
#pragma unroll
    for (int k = 0; k < KN; ++k) { kA[k] = 1e38f; kB[k] = 1e38f; }
#pragma unroll 1
    for (int j = 0; j < PP; j += 4) {
        float d0 = ni + sn[j]     - 2.f * (px * spx[j]     + py * spy[j]     + pz * spz[j]);
        float d1 = ni + sn[j + 1] - 2.f * (px * spx[j + 1] + py * spy[j + 1] + pz * spz[j + 1]);
        float d2 = ni + sn[j + 2] - 2.f * (px * spx[j + 2] + py * spy[j + 2] + pz * spz[j + 2]);
        float d3 = ni + sn[j + 3] - 2.f * (px * spx[j + 3] + py * spy[j + 3] + pz * spz[j + 3]);
        if (j == t)     d0 = 1e30f;
        if (j + 1 == t) d1 = 1e30f;
        if (j + 2 == t) d2 = 1e30f;
        if (j + 3 == t) d3 = 1e30f;
        ins20(kA, embed(d0, j));
        ins20(kA, embed(d2, j + 2));
        ins20(kB, embed(d1, j + 1));
        ins20(kB, embed(d3, j + 3));
    }

    float u1[16];
#pragma unroll
    for (int c = 0; c < 16; ++c) {
        u1[c] = b1s[c] + px * w1u[c] + py * w1u[16 + c] + pz * w1u[32 + c];
        v1s[t * 17 + c] = px * w1v[c] + py * w1v[16 + c] + pz * w1v[32 + c];
    }
    __syncthreads();

    // merge two sorted 20-lists -> set of 20 smallest
    unsigned ji[KN];
#pragma unroll
    for (int i = 0; i < KN; ++i)
        ji[i] = __float_as_uint(fminf(kA[i], kB[KN - 1 - i])) & 127u;
    unsigned* oi = g_idx1 + ((size_t)b * PP + t) * 5;
#pragma unroll
    for (int w = 0; w < 5; ++w)
        oi[w] = ji[4 * w] | (ji[4 * w + 1] << 8) | (ji[4 * w + 2] << 16) | (ji[4 * w + 3] << 24);

    // factored stats: sum h = 20u + Sv ; sum h^2 = 20u^2 + 2u*Sv + Sq
    float Sv[16], Sq[16];
#pragma unroll
    for (int c = 0; c < 16; ++c) { Sv[c] = 0.f; Sq[c] = 0.f; }
#pragma unroll
    for (int k = 0; k < KN; ++k) {
        int j = (int)ji[k];
#pragma unroll
        for (int c = 0; c < 16; ++c) {
            float v = v1s[j * 17 + c];
            Sv[c] += v; Sq[c] = fmaf(v, v, Sq[c]);
        }
    }
    float s[16], q[16];
#pragma unroll
    for (int c = 0; c < 16; ++c) {
        float u = u1[c];
        s[c] = fmaf(20.f, u, Sv[c]);
        q[c] = fmaf(20.f * u, u, fmaf(2.f * u, Sv[c], Sq[c]));
    }
#pragma unroll
    for (int c = 0; c < 16; ++c) {
        for (int o = 16; o > 0; o >>= 1) {
            s[c] += __shfl_xor_sync(0xffffffffu, s[c], o);
            q[c] += __shfl_xor_sync(0xffffffffu, q[c], o);
        }
    }
    int lane = t & 31, wid = t >> 5;
    if (lane == 0) {
#pragma unroll
        for (int c = 0; c < 16; ++c) { wpart[wid][c] = s[c]; wpart[wid][16 + c] = q[c]; }
    }
    __syncthreads();
    if (t < 32) {
        float v = wpart[0][t] + wpart[1][t] + wpart[2][t] + wpart[3][t];
        atomicAdd(&g_stats[t], v);
    }
}

// ------------------------------------------------------------------
// K2: h1 = relu(u1'+v1') with BN1 folded ; packed stats of h1@W2+b2
__global__ __launch_bounds__(128) void k2_stats2(
    const float* __restrict__ pos,
    const float* __restrict__ w1, const float* __restrict__ b1,
    const float* __restrict__ g1, const float* __restrict__ be1,
    const float* __restrict__ w2, const float* __restrict__ b2)
{
    __shared__ float v1s[PP * 17];
    __shared__ float w1u[48], w1v[48], b1s[16];
    __shared__ __align__(16) float sw2[256];
    __shared__ __align__(16) float sb2[16];
    __shared__ float bn1s[16], bn1o[16];
    __shared__ float wpart[4][32];

    int b = blockIdx.x, t = threadIdx.x;
    float px = pos[(b * PP + t) * 3 + 0];
    float py = pos[(b * PP + t) * 3 + 1];
    float pz = pos[(b * PP + t) * 3 + 2];
    if (t < 48) { w1u[t] = w1[t] - w1[t + 48]; w1v[t] = w1[t + 48]; }
    if (t < 16) b1s[t] = b1[t];
    sw2[t] = w2[t]; sw2[t + 128] = w2[t + 128];
    if (t < 16) sb2[t] = b2[t];
    if (t >= 32 && t < 48) {
        int c = t - 32;
        const float N = (float)BG * PP * KN;
        float m = g_stats[c] / N;
        float v = g_stats[16 + c] / N - m * m;
        float sc = g1[c] * rsqrtf(v + EPSB);
        bn1s[c] = sc; bn1o[c] = be1[c] - m * sc;
    }
    __syncthreads();

    // BN1 folded: u1' = u1*s+o ; v1' = v1*s
    float u1[16];
#pragma unroll
    for (int c = 0; c < 16; ++c) {
        float uu = b1s[c] + px * w1u[c] + py * w1u[16 + c] + pz * w1u[32 + c];
        float vv = px * w1v[c] + py * w1v[16 + c] + pz * w1v[32 + c];
        u1[c] = fmaf(uu, bn1s[c], bn1o[c]);
        v1s[t * 17 + c] = vv * bn1s[c];
    }
    __syncthreads();

    const unsigned* oi = g_idx1 + ((size_t)b * PP + t) * 5;
    const ulonglong2* sw2u2 = (const ulonglong2*)sw2;
    const u64* sb2u = (const u64*)sb2;

    u64 S[8], Q[8];
#pragma unroll
    for (int g = 0; g < 8; ++g) { S[g] = 0ull; Q[g] = 0ull; }
#pragma unroll 1
    for (int w = 0; w < 5; ++w) {
        unsigned pk = oi[w];
#pragma unroll 1
        for (int kk = 0; kk < 4; ++kk) {
            int j = (int)(pk & 255u); pk >>= 8;
            float h1[16];
#pragma unroll
            for (int c = 0; c < 16; ++c)
                h1[c] = fmaxf(u1[c] + v1s[j * 17 + c], 0.f);
            u64 A2[8];
#pragma unroll
            for (int g = 0; g < 8; ++g) A2[g] = sb2u[g];
#pragma unroll
            for (int f = 0; f < 16; ++f) {
                u64 hv = pk2(h1[f], h1[f]);
                ulonglong2 w0 = sw2u2[f * 4 + 0], w1q = sw2u2[f * 4 + 1];
                ulonglong2 w2q = sw2u2[f * 4 + 2], w3q = sw2u2[f * 4 + 3];
                A2[0] = fma2(hv, w0.x, A2[0]);  A2[1] = fma2(hv, w0.y, A2[1]);
                A2[2] = fma2(hv, w1q.x, A2[2]); A2[3] = fma2(hv, w1q.y, A2[3]);
                A2[4] = fma2(hv, w2q.x, A2[4]); A2[5] = fma2(hv, w2q.y, A2[5]);
                A2[6] = fma2(hv, w3q.x, A2[6]); A2[7] = fma2(hv, w3q.y, A2[7]);
            }
#pragma unroll
            for (int g = 0; g < 8; ++g) {
                S[g] = add2(S[g], A2[g]);
                Q[g] = fma2(A2[g], A2[g], Q[g]);
            }
        }
    }
    float s[16], q[16];
#pragma unroll
    for (int g = 0; g < 8; ++g) {
        upk2(s[2 * g], s[2 * g + 1], S[g]);
        upk2(q[2 * g], q[2 * g + 1], Q[g]);
    }
#pragma unroll
    for (int c = 0; c < 16; ++c) {
        for (int o = 16; o > 0; o >>= 1) {
            s[c] += __shfl_xor_sync(0xffffffffu, s[c], o);
            q[c] += __shfl_xor_sync(0xffffffffu, q[c], o);
        }
    }
    int lane = t & 31, wid = t >> 5;
    if (lane == 0) {
#pragma unroll
        for (int c = 0; c < 16; ++c) { wpart[wid][c] = s[c]; wpart[wid][16 + c] = q[c]; }
    }
    __syncthreads();
    if (t < 32) {
        float v = wpart[0][t] + wpart[1][t] + wpart[2][t] + wpart[3][t];
        atomicAdd(&g_stats[32 + t], v);
    }
}

// ------------------------------------------------------------------
// K3: conv1 (BN1+BN2 folded) -> x1 ; kNN2 ; conv2 ; lin1 ; head
__global__ __launch_bounds__(128, 1) void k3_mega(
    const float* __restrict__ pos,
    const float* __restrict__ w1, const float* __restrict__ b1,
    const float* __restrict__ g1, const float* __restrict__ be1,
    const float* __restrict__ w2, const float* __restrict__ b2,
    const float* __restrict__ g2, const float* __restrict__ be2,
    const float* __restrict__ w3, const float* __restrict__ b3,
    const float* __restrict__ c2w, const float* __restrict__ c2b,
    const float* __restrict__ lw,  const float* __restrict__ lb,
    const float* __restrict__ mw1, const float* __restrict__ mb1,
    const float* __restrict__ mw2, const float* __restrict__ mb2,
    const float* __restrict__ mw3, const float* __restrict__ mb3,
    float* __restrict__ out)
{
    __shared__ __align__(16) float pool[6784];
    __shared__ float sn2[PP];
    __shared__ unsigned char nb2[PP * KN];
    __shared__ float w1u[48], w1v[48], b1s[16], bn1s[16], bn1o[16];
    __shared__ __align__(16) float sw2[256];
    __shared__ __align__(16) float sw3[256];
    __shared__ __align__(16) float sb2[16];
    __shared__ float sb3[16], bn2s[16], bn2o[16];
    __shared__ __align__(16) float c2u[512];
    __shared__ __align__(16) float c2v[512];
    __shared__ __align__(16) float c2bs[32];
    __shared__ float wm[128 * 4];
    __shared__ float gvec[128], h1s[64], h2s[64], outs[2];

    int b = blockIdx.x, t = threadIdx.x;
    int lane = t & 31, wid = t >> 5;
    float px = pos[(b * PP + t) * 3 + 0];
    float py = pos[(b * PP + t) * 3 + 1];
    float pz = pos[(b * PP + t) * 3 + 2];
    if (t < 48) { w1u[t] = w1[t] - w1[t + 48]; w1v[t] = w1[t + 48]; }
    if (t < 16) { b1s[t] = b1[t]; sb3[t] = b3[t]; }
    sw2[t] = w2[t]; sw2[t + 128] = w2[t + 128];
    sw3[t] = w3[t]; sw3[t + 128] = w3[t + 128];
#pragma unroll
    for (int i = t; i < 512; i += 128) { c2u[i] = c2w[i] - c2w[i + 512]; c2v[i] = c2w[i + 512]; }
    if (t < 32) c2bs[t] = c2b[t];
    {
        const float N = (float)BG * PP * KN;
        if (t >= 64 && t < 80) {
            int c = t - 64;
            float m = g_stats[c] / N;
            float v = g_stats[16 + c] / N - m * m;
            float sc = g1[c] * rsqrtf(v + EPSB);
            bn1s[c] = sc; bn1o[c] = be1[c] - m * sc;
        } else if (t >= 80 && t < 96) {
            int c = t - 80;
            float m = g_stats[32 + c] / N;
            float v = g_stats[48 + c] / N - m * m;
            float sc = g2[c] * rsqrtf(v + EPSB);
            bn2s[c] = sc; bn2o[c] = be2[c] - m * sc;
        }
    }
    __syncthreads();   // raw weights + bn consts ready; pool free

    // fold BN2 into sw2 (in place) and bias sb2 = b2*s + o
    {
        float s0 = bn2s[t & 15];
        sw2[t] *= s0;
        sw2[t + 128] *= s0;
        if (t < 16) sb2[t] = fmaf(b2[t], bn2s[t], bn2o[t]);
    }

    // phase A with BN1 folded: u1' = u1*s+o (regs), v1' = v1*s (pool)
    float u1[16];
    {
        float vv[16];
#pragma unroll
        for (int c = 0; c < 16; ++c) {
            float uu = b1s[c] + px * w1u[c] + py * w1u[16 + c] + pz * w1u[32 + c];
            u1[c] = fmaf(uu, bn1s[c], bn1o[c]);
            vv[c] = (px * w1v[c] + py * w1v[16 + c] + pz * w1v[32 + c]) * bn1s[c];
        }
        float4* vr = (float4*)pool + t * 5;
#pragma unroll
        for (int g = 0; g < 4; ++g)
            vr[g] = make_float4(vv[4 * g], vv[4 * g + 1], vv[4 * g + 2], vv[4 * g + 3]);
    }
    __syncthreads();   // covers sw2 scaling + pool writes

    // ---- conv1 over 20 edges (folded BN; packed f32x2 layers) ----
    const unsigned* oi = g_idx1 + ((size_t)b * PP + t) * 5;
    const ulonglong2* sw2u2 = (const ulonglong2*)sw2;
    const ulonglong2* sw3u2 = (const ulonglong2*)sw3;
    const u64* sb2u = (const u64*)sb2;
    float x1a[16];
#pragma unroll
    for (int c = 0; c < 16; ++c) x1a[c] = -1e30f;
#pragma unroll 1
    for (int w = 0; w < 5; ++w) {
        unsigned pk = oi[w];
#pragma unroll 1
        for (int kk = 0; kk < 4; ++kk) {
            int j = (int)(pk & 255u); pk >>= 8;
            const float4* vp = (const float4*)pool + j * 5;
            float4 q0 = vp[0], q1 = vp[1], q2 = vp[2], q3 = vp[3];
            float h1v[16];
            h1v[0]  = fmaxf(u1[0]  + q0.x, 0.f);
            h1v[1]  = fmaxf(u1[1]  + q0.y, 0.f);
            h1v[2]  = fmaxf(u1[2]  + q0.z, 0.f);
            h1v[3]  = fmaxf(u1[3]  + q0.w, 0.f);
            h1v[4]  = fmaxf(u1[4]  + q1.x, 0.f);
            h1v[5]  = fmaxf(u1[5]  + q1.y, 0.f);
            h1v[6]  = fmaxf(u1[6]  + q1.z, 0.f);
            h1v[7]  = fmaxf(u1[7]  + q1.w, 0.f);
            h1v[8]  = fmaxf(u1[8]  + q2.x, 0.f);
            h1v[9]  = fmaxf(u1[9]  + q2.y, 0.f);
            h1v[10] = fmaxf(u1[10] + q2.z, 0.f);
            h1v[11] = fmaxf(u1[11] + q2.w, 0.f);
            h1v[12] = fmaxf(u1[12] + q3.x, 0.f);
            h1v[13] = fmaxf(u1[13] + q3.y, 0.f);
            h1v[14] = fmaxf(u1[14] + q3.z, 0.f);
            h1v[15] = fmaxf(u1[15] + q3.w, 0.f);

            u64 A2[8];
#pragma unroll
            for (int g = 0; g < 8; ++g) A2[g] = sb2u[g];
#pragma unroll
            for (int f = 0; f < 16; ++f) {
                u64 hv = pk2(h1v[f], h1v[f]);
                ulonglong2 w0 = sw2u2[f * 4 + 0], w1q = sw2u2[f * 4 + 1];
                ulonglong2 w2q = sw2u2[f * 4 + 2], w3q = sw2u2[f * 4 + 3];
                A2[0] = fma2(hv, w0.x, A2[0]);  A2[1] = fma2(hv, w0.y, A2[1]);
                A2[2] = fma2(hv, w1q.x, A2[2]); A2[3] = fma2(hv, w1q.y, A2[3]);
                A2[4] = fma2(hv, w2q.x, A2[4]); A2[5] = fma2(hv, w2q.y, A2[5]);
                A2[6] = fma2(hv, w3q.x, A2[6]); A2[7] = fma2(hv, w3q.y, A2[7]);
            }
            float h2v[16];
#pragma unroll
            for (int g = 0; g < 8; ++g) {
                float a, bb; upk2(a, bb, A2[g]);
                h2v[2 * g]     = fmaxf(a,  0.f);
                h2v[2 * g + 1] = fmaxf(bb, 0.f);
            }
            u64 A3[8];
#pragma unroll
            for (int g = 0; g < 8; ++g) A3[g] = 0ull;
#pragma unroll
            for (int f = 0; f < 16; ++f) {
                u64 hv = pk2(h2v[f], h2v[f]);
                ulonglong2 w0 = sw3u2[f * 4 + 0], w1q = sw3u2[f * 4 + 1];
                ulonglong2 w2q = sw3u2[f * 4 + 2], w3q = sw3u2[f * 4 + 3];
                A3[0] = fma2(hv, w0.x, A3[0]);  A3[1] = fma2(hv, w0.y, A3[1]);
                A3[2] = fma2(hv, w1q.x, A3[2]); A3[3] = fma2(hv, w1q.y, A3[3]);
                A3[4] = fma2(hv, w2q.x, A3[4]); A3[5] = fma2(hv, w2q.y, A3[5]);
                A3[6] = fma2(hv, w3q.x, A3[6]); A3[7] = fma2(hv, w3q.y, A3[7]);
            }
#pragma unroll
            for (int g = 0; g < 8; ++g) {
                float a, bb; upk2(a, bb, A3[g]);
                x1a[2 * g]     = fmaxf(x1a[2 * g],     a);
                x1a[2 * g + 1] = fmaxf(x1a[2 * g + 1], bb);
            }
        }
    }
    float x1f[16];
    float n2 = 0.f;
#pragma unroll
    for (int c = 0; c < 16; ++c) { x1f[c] = x1a[c] + sb3[c]; n2 = fmaf(x1f[c], x1f[c], n2); }
    __syncthreads();   // all v1 reads done
    {
        float4* xr = (float4*)pool + t * 5;
#pragma unroll
        for (int g = 0; g < 4; ++g)
            xr[g] = make_float4(x1f[4 * g], x1f[4 * g + 1], x1f[4 * g + 2], x1f[4 * g + 3]);
        sn2[t] = n2;
    }
    __syncthreads();

    // ---- kNN2: 4 candidates/iter, packed f32x2 dots, 2 inserts per list ----
    u64 xq[8];
#pragma unroll
    for (int g = 0; g < 8; ++g) xq[g] = pk2(x1f[2 * g], x1f[2 * g + 1]);

    float kA[KN], kB[KN];
#pragma unroll
    for (int k = 0; k < KN; ++k) { kA[k] = 1e38f; kB[k] = 1e38f; }
#pragma unroll 1
    for (int j = 0; j < PP; j += 4) {
        float dd[4];
#pragma unroll
        for (int s = 0; s < 4; ++s) {
            const ulonglong2* rp = (const ulonglong2*)(pool + (j + s) * 20);
            ulonglong2 r0 = rp[0], r1 = rp[1], r2 = rp[2], r3 = rp[3];
            u64 a0 = 0ull, a1 = 0ull;
            a0 = fma2(xq[0], r0.x, a0); a1 = fma2(xq[1], r0.y, a1);
            a0 = fma2(xq[2], r1.x, a0); a1 = fma2(xq[3], r1.y, a1);
            a0 = fma2(xq[4], r2.x, a0); a1 = fma2(xq[5], r2.y, a1);
            a0 = fma2(xq[6], r3.x, a0); a1 = fma2(xq[7], r3.y, a1);
            float l0, h0, l1, h1; upk2(l0, h0, a0); upk2(l1, h1, a1);
            float dot = (l0 + h0) + (l1 + h1);
            dd[s] = n2 + sn2[j + s] - 2.f * dot;
        }
        if (j == t)     dd[0] = 1e30f;
        if (j + 1 == t) dd[1] = 1e30f;
        if (j + 2 == t) dd[2] = 1e30f;
        if (j + 3 == t) dd[3] = 1e30f;
        ins20(kA, embed(dd[0], j));
        ins20(kA, embed(dd[2], j + 2));
        ins20(kB, embed(dd[1], j + 1));
        ins20(kB, embed(dd[3], j + 3));
    }
#pragma unroll
    for (int k = 0; k < KN; ++k)
        nb2[t * KN + k] = (unsigned char)(__float_as_uint(fminf(kA[k], kB[KN - 1 - k])) & 127u);

    // ---- conv2: v2 = x1f@Wv -> smem (stride 33); x2 = u2 + max_k v2[j] ----
    float* v2s = pool + 2560;
    {
        const ulonglong2* cv = (const ulonglong2*)c2v;
        u64 V[16];
#pragma unroll
        for (int g = 0; g < 16; ++g) V[g] = 0ull;
#pragma unroll
        for (int f = 0; f < 16; ++f) {
            u64 hv = pk2(x1f[f], x1f[f]);
#pragma unroll
            for (int g = 0; g < 8; ++g) {
                ulonglong2 wv = cv[f * 8 + g];
                V[2 * g]     = fma2(hv, wv.x, V[2 * g]);
                V[2 * g + 1] = fma2(hv, wv.y, V[2 * g + 1]);
            }
        }
#pragma unroll
        for (int g = 0; g < 16; ++g) {
            float a, bb; upk2(a, bb, V[g]);
            v2s[t * 33 + 2 * g] = a; v2s[t * 33 + 2 * g + 1] = bb;
        }
    }
    __syncthreads();

    float x2m[32];
#pragma unroll
    for (int c = 0; c < 32; ++c) x2m[c] = -1e30f;
#pragma unroll 1
    for (int k = 0; k < KN; ++k) {
        int j = (int)nb2[t * KN + k];
#pragma unroll
        for (int c = 0; c < 32; ++c) x2m[c] = fmaxf(x2m[c], v2s[j * 33 + c]);
    }
    float x2a[32];
    {
        const ulonglong2* cu = (const ulonglong2*)c2u;
        const u64* cbu = (const u64*)c2bs;
        u64 U[16];
#pragma unroll
        for (int g = 0; g < 16; ++g) U[g] = cbu[g];
#pragma unroll
        for (int f = 0; f < 16; ++f) {
            u64 hv = pk2(x1f[f], x1f[f]);
#pragma unroll
            for (int g = 0; g < 8; ++g) {
                ulonglong2 wv = cu[f * 8 + g];
                U[2 * g]     = fma2(hv, wv.x, U[2 * g]);
                U[2 * g + 1] = fma2(hv, wv.y, U[2 * g + 1]);
            }
        }
#pragma unroll
        for (int g = 0; g < 16; ++g) {
            float a, bb; upk2(a, bb, U[g]);
            x2a[2 * g]     = a  + x2m[2 * g];
            x2a[2 * g + 1] = bb + x2m[2 * g + 1];
        }
    }
    __syncthreads();   // all v2/x1s reads done; pool free

    // ---- load lin1 weights transposed: lwt[c][f] = lw[f][c] ----
#pragma unroll 1
    for (int i = t; i < 48 * 128; i += 128) {
        int c = i / 48, f = i - c * 48;
        pool[i] = lw[f * 128 + c];
    }
    __syncthreads();

    // ---- lin1: per-channel broadcast dot + shuffle/cross-warp max (unroll 4) ----
    u64 F2[24];
#pragma unroll
    for (int g = 0; g < 8; ++g)  F2[g]     = pk2(x1f[2 * g], x1f[2 * g + 1]);
#pragma unroll
    for (int g = 0; g < 16; ++g) F2[8 + g] = pk2(x2a[2 * g], x2a[2 * g + 1]);
#pragma unroll 4
    for (int c = 0; c < 128; ++c) {
        const ulonglong2* rw = (const ulonglong2*)(pool + c * 48);
        u64 a0 = 0ull, a1 = 0ull;
#pragma unroll
        for (int g = 0; g < 12; ++g) {
            ulonglong2 wv = rw[g];
            a0 = fma2(F2[2 * g],     wv.x, a0);
            a1 = fma2(F2[2 * g + 1], wv.y, a1);
        }
        float lo, hi; upk2(lo, hi, add2(a0, a1));
        float v = lo + hi;
#pragma unroll
        for (int o = 16; o > 0; o >>= 1)
            v = fmaxf(v, __shfl_xor_sync(0xffffffffu, v, o));
        if (lane == 0) wm[c * 4 + wid] = v;
    }
    __syncthreads();
    gvec[t] = fmaxf(fmaxf(wm[t * 4 + 0], wm[t * 4 + 1]),
                    fmaxf(wm[t * 4 + 2], wm[t * 4 + 3])) + __ldg(lb + t);
    __syncthreads();

    // ---- head MLP 128->64->64->2 + log_softmax ----
    if (t < 64) {
        float a = mb1[t];
#pragma unroll 4
        for (int i = 0; i < 128; ++i) a = fmaf(gvec[i], mw1[i * 64 + t], a);
        h1s[t] = fmaxf(a, 0.f);
    }
    __syncthreads();
    if (t < 64) {
        float a = mb2[t];
#pragma unroll 4
        for (int i = 0; i < 64; ++i) a = fmaf(h1s[i], mw2[i * 64 + t], a);
        h2s[t] = fmaxf(a, 0.f);
    }
    __syncthreads();
    if (t < 2) {
        float a = mb3[t];
#pragma unroll 4
        for (int i = 0; i < 64; ++i) a = fmaf(h2s[i], mw3[i * 2 + t], a);
        outs[t] = a;
    }
    __syncthreads();
    if (t == 0) {
        float o0 = outs[0], o1 = outs[1];
        float m = fmaxf(o0, o1);
        float lse = m + logf(expf(o0 - m) + expf(o1 - m));
        out[b * 2 + 0] = o0 - lse;
        out[b * 2 + 1] = o1 - lse;
    }
}

// ------------------------------------------------------------------
extern "C" void kernel_launch(void* const* d_in, const int* in_sizes, int n_in,
                              void* d_out, int out_size)
{
    (void)in_sizes; (void)n_in; (void)out_size;
    const float* pos   = (const float*)d_in[0];
    const float* c1_w1 = (const float*)d_in[2];
    const float* c1_b1 = (const float*)d_in[3];
    const float* c1_g1 = (const float*)d_in[4];
    const float* c1_be1= (const float*)d_in[5];
    const float* c1_w2 = (const float*)d_in[6];
    const float* c1_b2 = (const float*)d_in[7];
    const float* c1_g2 = (const float*)d_in[8];
    const float* c1_be2= (const float*)d_in[9];
    const float* c1_w3 = (const float*)d_in[10];
    const float* c1_b3 = (const float*)d_in[11];
    const float* c2_w  = (const float*)d_in[12];
    const float* c2_b  = (const float*)d_in[13];
    const float* lw    = (const float*)d_in[14];
    const float* lb    = (const float*)d_in[15];
    const float* m_w1  = (const float*)d_in[16];
    const float* m_b1  = (const float*)d_in[17];
    const float* m_w2  = (const float*)d_in[18];
    const float* m_b2  = (const float*)d_in[19];
    const float* m_w3  = (const float*)d_in[20];
    const float* m_b3  = (const float*)d_in[21];
    float* out = (float*)d_out;

    k0_zero<<<1, 64>>>();
    k1_knn_stats<<<BG, 128>>>(pos, c1_w1, c1_b1);
    k2_stats2<<<BG, 128>>>(pos, c1_w1, c1_b1, c1_g1, c1_be1, c1_w2, c1_b2);
    k3_mega<<<BG, 128>>>(pos,
                         c1_w1, c1_b1, c1_g1, c1_be1,
                         c1_w2, c1_b2, c1_g2, c1_be2,
                         c1_w3, c1_b3,
                         c2_w, c2_b, lw, lb,
                         m_w1, m_b1, m_w2, m_b2, m_w3, m_b3,
                         out);
}

// round 15
// speedup vs baseline: 1.2034x; 1.0866x over previous
#include <cuda_runtime.h>
#include <math.h>

#define BG 1024
#define PP 128
#define KN 20
#define EPSB 1e-5f

typedef unsigned long long u64;

// ---- persistent scratch ----
__device__ unsigned int g_idx1[BG * PP * 5];        // 20 packed neighbor bytes per point
__device__ float g_stats[64];                       // sum1/sq1/sum2/sq2
__device__ float g_a2[(size_t)BG * PP * KN * 16];   // 160MB: per-edge A2 = h1@W2+b2

__global__ void k0_zero() { if (threadIdx.x < 64) g_stats[threadIdx.x] = 0.f; }

__device__ __forceinline__ float embed(float d2, int j) {
    return __uint_as_float((__float_as_uint(d2) & 0xFFFFFF80u) | (unsigned)j);
}
__device__ __forceinline__ u64 pk2(float a, float b) {
    u64 r; asm("mov.b64 %0,{%1,%2};" : "=l"(r) : "f"(a), "f"(b)); return r;
}
__device__ __forceinline__ void upk2(float& a, float& b, u64 v) {
    asm("mov.b64 {%0,%1},%2;" : "=f"(a), "=f"(b) : "l"(v));
}
__device__ __forceinline__ u64 fma2(u64 a, u64 b, u64 c) {
    u64 d; asm("fma.rn.f32x2 %0,%1,%2,%3;" : "=l"(d) : "l"(a), "l"(b), "l"(c)); return d;
}
__device__ __forceinline__ u64 add2(u64 a, u64 b) {
    u64 d; asm("add.rn.f32x2 %0,%1,%2;" : "=l"(d) : "l"(a), "l"(b)); return d;
}
__device__ __forceinline__ void ins20(float (&kd)[KN], float dv) {
    kd[KN - 1] = fminf(kd[KN - 1], dv);
#pragma unroll
    for (int p = KN - 1; p > 0; --p) {
        float lo = fminf(kd[p - 1], kd[p]);
        float hi = fmaxf(kd[p - 1], kd[p]);
        kd[p - 1] = lo; kd[p] = hi;
    }
}

// ------------------------------------------------------------------
// K1: kNN on pos (2 lists, 4 cand/iter) + factored BN1 pre-activation stats
__global__ __launch_bounds__(128) void k1_knn_stats(
    const float* __restrict__ pos,
    const float* __restrict__ w1, const float* __restrict__ b1)
{
    __shared__ float spx[PP], spy[PP], spz[PP], sn[PP];
    __shared__ float v1s[PP * 17];
    __shared__ float w1u[48], w1v[48], b1s[16];
    __shared__ float wpart[4][32];

    int b = blockIdx.x, t = threadIdx.x;
    float px = pos[(b * PP + t) * 3 + 0];
    float py = pos[(b * PP + t) * 3 + 1];
    float pz = pos[(b * PP + t) * 3 + 2];
    spx[t] = px; spy[t] = py; spz[t] = pz;
    if (t < 48) { w1u[t] = w1[t] - w1[t + 48]; w1v[t] = w1[t + 48]; }
    if (t < 16) b1s[t] = b1[t];
    float ni = px * px + py * py + pz * pz;
    sn[t] = ni;
    __syncthreads();

    float kA[KN], kB[KN];
#pragma unroll
    for (int k = 0; k < KN; ++k) { kA[k] = 1e38f; kB[k] = 1e38f; }
#pragma unroll 1
    for (int j = 0; j < PP; j += 4) {
        float d0 = ni + sn[j]     - 2.f * (px * spx[j]     + py * spy[j]     + pz * spz[j]);
        float d1 = ni + sn[j + 1] - 2.f * (px * spx[j + 1] + py * spy[j + 1] + pz * spz[j + 1]);
        float d2 = ni + sn[j + 2] - 2.f * (px * spx[j + 2] + py * spy[j + 2] + pz * spz[j + 2]);
        float d3 = ni + sn[j + 3] - 2.f * (px * spx[j + 3] + py * spy[j + 3] + pz * spz[j + 3]);
        if (j == t)     d0 = 1e30f;
        if (j + 1 == t) d1 = 1e30f;
        if (j + 2 == t) d2 = 1e30f;
        if (j + 3 == t) d3 = 1e30f;
        ins20(kA, embed(d0, j));
        ins20(kA, embed(d2, j + 2));
        ins20(kB, embed(d1, j + 1));
        ins20(kB, embed(d3, j + 3));
    }

    float u1[16];
#pragma unroll
    for (int c = 0; c < 16; ++c) {
        u1[c] = b1s[c] + px * w1u[c] + py * w1u[16 + c] + pz * w1u[32 + c];
        v1s[t * 17 + c] = px * w1v[c] + py * w1v[16 + c] + pz * w1v[32 + c];
    }
    __syncthreads();

    unsigned ji[KN];
#pragma unroll
    for (int i = 0; i < KN; ++i)
        ji[i] = __float_as_uint(fminf(kA[i], kB[KN - 1 - i])) & 127u;
    unsigned* oi = g_idx1 + ((size_t)b * PP + t) * 5;
#pragma unroll
    for (int w = 0; w < 5; ++w)
        oi[w] = ji[4 * w] | (ji[4 * w + 1] << 8) | (ji[4 * w + 2] << 16) | (ji[4 * w + 3] << 24);

    // factored stats: sum h = 20u + Sv ; sum h^2 = 20u^2 + 2u*Sv + Sq
    float Sv[16], Sq[16];
#pragma unroll
    for (int c = 0; c < 16; ++c) { Sv[c] = 0.f; Sq[c] = 0.f; }
#pragma unroll
    for (int k = 0; k < KN; ++k) {
        int j = (int)ji[k];
#pragma unroll
        for (int c = 0; c < 16; ++c) {
            float v = v1s[j * 17 + c];
            Sv[c] += v; Sq[c] = fmaf(v, v, Sq[c]);
        }
    }
    float s[16], q[16];
#pragma unroll
    for (int c = 0; c < 16; ++c) {
        float u = u1[c];
        s[c] = fmaf(20.f, u, Sv[c]);
        q[c] = fmaf(20.f * u, u, fmaf(2.f * u, Sv[c], Sq[c]));
    }
#pragma unroll
    for (int c = 0; c < 16; ++c) {
        for (int o = 16; o > 0; o >>= 1) {
            s[c] += __shfl_xor_sync(0xffffffffu, s[c], o);
            q[c] += __shfl_xor_sync(0xffffffffu, q[c], o);
        }
    }
    int lane = t & 31, wid = t >> 5;
    if (lane == 0) {
#pragma unroll
        for (int c = 0; c < 16; ++c) { wpart[wid][c] = s[c]; wpart[wid][16 + c] = q[c]; }
    }
    __syncthreads();
    if (t < 32) {
        float v = wpart[0][t] + wpart[1][t] + wpart[2][t] + wpart[3][t];
        atomicAdd(&g_stats[t], v);
    }
}

// ------------------------------------------------------------------
// K2: h1 = relu(u1'+v1') (BN1 folded); A2 = h1@W2+b2 -> stats AND store to g_a2
__global__ __launch_bounds__(128) void k2_stats2(
    const float* __restrict__ pos,
    const float* __restrict__ w1, const float* __restrict__ b1,
    const float* __restrict__ g1, const float* __restrict__ be1,
    const float* __restrict__ w2, const float* __restrict__ b2)
{
    __shared__ float v1s[PP * 17];
    __shared__ float w1u[48], w1v[48], b1s[16];
    __shared__ __align__(16) float sw2[256];
    __shared__ __align__(16) float sb2[16];
    __shared__ float bn1s[16], bn1o[16];
    __shared__ float wpart[4][32];

    int b = blockIdx.x, t = threadIdx.x;
    float px = pos[(b * PP + t) * 3 + 0];
    float py = pos[(b * PP + t) * 3 + 1];
    float pz = pos[(b * PP + t) * 3 + 2];
    if (t < 48) { w1u[t] = w1[t] - w1[t + 48]; w1v[t] = w1[t + 48]; }
    if (t < 16) b1s[t] = b1[t];
    sw2[t] = w2[t]; sw2[t + 128] = w2[t + 128];
    if (t < 16) sb2[t] = b2[t];
    if (t >= 32 && t < 48) {
        int c = t - 32;
        const float N = (float)BG * PP * KN;
        float m = g_stats[c] / N;
        float v = g_stats[16 + c] / N - m * m;
        float sc = g1[c] * rsqrtf(v + EPSB);
        bn1s[c] = sc; bn1o[c] = be1[c] - m * sc;
    }
    __syncthreads();

    float u1[16];
#pragma unroll
    for (int c = 0; c < 16; ++c) {
        float uu = b1s[c] + px * w1u[c] + py * w1u[16 + c] + pz * w1u[32 + c];
        float vv = px * w1v[c] + py * w1v[16 + c] + pz * w1v[32 + c];
        u1[c] = fmaf(uu, bn1s[c], bn1o[c]);
        v1s[t * 17 + c] = vv * bn1s[c];
    }
    __syncthreads();

    const unsigned* oi = g_idx1 + ((size_t)b * PP + t) * 5;
    const ulonglong2* sw2u2 = (const ulonglong2*)sw2;
    const u64* sb2u = (const u64*)sb2;
    float4* ga = (float4*)(g_a2 + (((size_t)b * PP + t) * KN) * 16);

    u64 S[8], Q[8];
#pragma unroll
    for (int g = 0; g < 8; ++g) { S[g] = 0ull; Q[g] = 0ull; }
#pragma unroll 1
    for (int w = 0; w < 5; ++w) {
        unsigned pk = oi[w];
#pragma unroll 1
        for (int kk = 0; kk < 4; ++kk) {
            int j = (int)(pk & 255u); pk >>= 8;
            float h1[16];
#pragma unroll
            for (int c = 0; c < 16; ++c)
                h1[c] = fmaxf(u1[c] + v1s[j * 17 + c], 0.f);
            u64 A2[8];
#pragma unroll
            for (int g = 0; g < 8; ++g) A2[g] = sb2u[g];
#pragma unroll
            for (int f = 0; f < 16; ++f) {
                u64 hv = pk2(h1[f], h1[f]);
                ulonglong2 w0 = sw2u2[f * 4 + 0], w1q = sw2u2[f * 4 + 1];
                ulonglong2 w2q = sw2u2[f * 4 + 2], w3q = sw2u2[f * 4 + 3];
                A2[0] = fma2(hv, w0.x, A2[0]);  A2[1] = fma2(hv, w0.y, A2[1]);
                A2[2] = fma2(hv, w1q.x, A2[2]); A2[3] = fma2(hv, w1q.y, A2[3]);
                A2[4] = fma2(hv, w2q.x, A2[4]); A2[5] = fma2(hv, w2q.y, A2[5]);
                A2[6] = fma2(hv, w3q.x, A2[6]); A2[7] = fma2(hv, w3q.y, A2[7]);
            }
            // store A2 for k3 (coalesced STG.128 x4)
            {
                int e = w * 4 + kk;
                float a0, a1, a2, a3;
#pragma unroll
                for (int g = 0; g < 4; ++g) {
                    upk2(a0, a1, A2[2 * g]); upk2(a2, a3, A2[2 * g + 1]);
                    ga[e * 4 + g] = make_float4(a0, a1, a2, a3);
                }
            }
#pragma unroll
            for (int g = 0; g < 8; ++g) {
                S[g] = add2(S[g], A2[g]);
                Q[g] = fma2(A2[g], A2[g], Q[g]);
            }
        }
    }
    float s[16], q[16];
#pragma unroll
    for (int g = 0; g < 8; ++g) {
        upk2(s[2 * g], s[2 * g + 1], S[g]);
        upk2(q[2 * g], q[2 * g + 1], Q[g]);
    }
#pragma unroll
    for (int c = 0; c < 16; ++c) {
        for (int o = 16; o > 0; o >>= 1) {
            s[c] += __shfl_xor_sync(0xffffffffu, s[c], o);
            q[c] += __shfl_xor_sync(0xffffffffu, q[c], o);
        }
    }
    int lane = t & 31, wid = t >> 5;
    if (lane == 0) {
#pragma unroll
        for (int c = 0; c < 16; ++c) { wpart[wid][c] = s[c]; wpart[wid][16 + c] = q[c]; }
    }
    __syncthreads();
    if (t < 32) {
        float v = wpart[0][t] + wpart[1][t] + wpart[2][t] + wpart[3][t];
        atomicAdd(&g_stats[32 + t], v);
    }
}

// ------------------------------------------------------------------
// K3: conv1 from precomputed A2 (load, bn2-relu, W3 GEMV, max) -> x1 ;
//     kNN2 ; conv2 ; lin1 ; head
__global__ __launch_bounds__(128, 1) void k3_mega(
    const float* __restrict__ g1, const float* __restrict__ be1,
    const float* __restrict__ g2, const float* __restrict__ be2,
    const float* __restrict__ w3, const float* __restrict__ b3,
    const float* __restrict__ c2w, const float* __restrict__ c2b,
    const float* __restrict__ lw,  const float* __restrict__ lb,
    const float* __restrict__ mw1, const float* __restrict__ mb1,
    const float* __restrict__ mw2, const float* __restrict__ mb2,
    const float* __restrict__ mw3, const float* __restrict__ mb3,
    float* __restrict__ out)
{
    __shared__ __align__(16) float pool[6784];
    __shared__ float sn2[PP];
    __shared__ unsigned char nb2[PP * KN];
    __shared__ __align__(16) float sw3[256];
    __shared__ float sb3[16], bn2s[16], bn2o[16];
    __shared__ __align__(16) float c2u[512];
    __shared__ __align__(16) float c2v[512];
    __shared__ __align__(16) float c2bs[32];
    __shared__ float wm[128 * 4];
    __shared__ float gvec[128], h1s[64], h2s[64], outs[2];

    int b = blockIdx.x, t = threadIdx.x;
    int lane = t & 31, wid = t >> 5;
    if (t < 16) sb3[t] = b3[t];
    sw3[t] = w3[t]; sw3[t + 128] = w3[t + 128];
#pragma unroll
    for (int i = t; i < 512; i += 128) { c2u[i] = c2w[i] - c2w[i + 512]; c2v[i] = c2w[i + 512]; }
    if (t < 32) c2bs[t] = c2b[t];
    if (t >= 80 && t < 96) {
        int c = t - 80;
        const float N = (float)BG * PP * KN;
        float m = g_stats[32 + c] / N;
        float v = g_stats[48 + c] / N - m * m;
        float sc = g2[c] * rsqrtf(v + EPSB);
        bn2s[c] = sc; bn2o[c] = be2[c] - m * sc;
    }
    __syncthreads();   // weights + bn2 consts ready

    // ---- conv1: stream A2 edges from global, bn2-relu, GEMV W3, max ----
    const ulonglong2* sw3u2 = (const ulonglong2*)sw3;
    const float4* ga = (const float4*)(g_a2 + (((size_t)b * PP + t) * KN) * 16);
    float x1a[16];
#pragma unroll
    for (int c = 0; c < 16; ++c) x1a[c] = -1e30f;
#pragma unroll 1
    for (int k = 0; k < KN; ++k) {
        float4 e0 = ga[k * 4 + 0], e1 = ga[k * 4 + 1];
        float4 e2 = ga[k * 4 + 2], e3 = ga[k * 4 + 3];
        float h2v[16];
        h2v[0]  = fmaxf(fmaf(e0.x, bn2s[0],  bn2o[0]),  0.f);
        h2v[1]  = fmaxf(fmaf(e0.y, bn2s[1],  bn2o[1]),  0.f);
        h2v[2]  = fmaxf(fmaf(e0.z, bn2s[2],  bn2o[2]),  0.f);
        h2v[3]  = fmaxf(fmaf(e0.w, bn2s[3],  bn2o[3]),  0.f);
        h2v[4]  = fmaxf(fmaf(e1.x, bn2s[4],  bn2o[4]),  0.f);
        h2v[5]  = fmaxf(fmaf(e1.y, bn2s[5],  bn2o[5]),  0.f);
        h2v[6]  = fmaxf(fmaf(e1.z, bn2s[6],  bn2o[6]),  0.f);
        h2v[7]  = fmaxf(fmaf(e1.w, bn2s[7],  bn2o[7]),  0.f);
        h2v[8]  = fmaxf(fmaf(e2.x, bn2s[8],  bn2o[8]),  0.f);
        h2v[9]  = fmaxf(fmaf(e2.y, bn2s[9],  bn2o[9]),  0.f);
        h2v[10] = fmaxf(fmaf(e2.z, bn2s[10], bn2o[10]), 0.f);
        h2v[11] = fmaxf(fmaf(e2.w, bn2s[11], bn2o[11]), 0.f);
        h2v[12] = fmaxf(fmaf(e3.x, bn2s[12], bn2o[12]), 0.f);
        h2v[13] = fmaxf(fmaf(e3.y, bn2s[13], bn2o[13]), 0.f);
        h2v[14] = fmaxf(fmaf(e3.z, bn2s[14], bn2o[14]), 0.f);
        h2v[15] = fmaxf(fmaf(e3.w, bn2s[15], bn2o[15]), 0.f);

        u64 A3[8];
#pragma unroll
        for (int g = 0; g < 8; ++g) A3[g] = 0ull;
#pragma unroll
        for (int f = 0; f < 16; ++f) {
            u64 hv = pk2(h2v[f], h2v[f]);
            ulonglong2 w0 = sw3u2[f * 4 + 0], w1q = sw3u2[f * 4 + 1];
            ulonglong2 w2q = sw3u2[f * 4 + 2], w3q = sw3u2[f * 4 + 3];
            A3[0] = fma2(hv, w0.x, A3[0]);  A3[1] = fma2(hv, w0.y, A3[1]);
            A3[2] = fma2(hv, w1q.x, A3[2]); A3[3] = fma2(hv, w1q.y, A3[3]);
            A3[4] = fma2(hv, w2q.x, A3[4]); A3[5] = fma2(hv, w2q.y, A3[5]);
            A3[6] = fma2(hv, w3q.x, A3[6]); A3[7] = fma2(hv, w3q.y, A3[7]);
        }
#pragma unroll
        for (int g = 0; g < 8; ++g) {
            float a, bb; upk2(a, bb, A3[g]);
            x1a[2 * g]     = fmaxf(x1a[2 * g],     a);
            x1a[2 * g + 1] = fmaxf(x1a[2 * g + 1], bb);
        }
    }
    float x1f[16];
    float n2 = 0.f;
#pragma unroll
    for (int c = 0; c < 16; ++c) { x1f[c] = x1a[c] + sb3[c]; n2 = fmaf(x1f[c], x1f[c], n2); }
    {
        float4* xr = (float4*)pool + t * 5;
#pragma unroll
        for (int g = 0; g < 4; ++g)
            xr[g] = make_float4(x1f[4 * g], x1f[4 * g + 1], x1f[4 * g + 2], x1f[4 * g + 3]);
        sn2[t] = n2;
    }
    __syncthreads();

    // ---- kNN2: 4 candidates/iter, packed f32x2 dots, 2 inserts per list ----
    u64 xq[8];
#pragma unroll
    for (int g = 0; g < 8; ++g) xq[g] = pk2(x1f[2 * g], x1f[2 * g + 1]);

    float kA[KN], kB[KN];
#pragma unroll
    for (int k = 0; k < KN; ++k) { kA[k] = 1e38f; kB[k] = 1e38f; }
#pragma unroll 1
    for (int j = 0; j < PP; j += 4) {
        float dd[4];
#pragma unroll
        for (int s = 0; s < 4; ++s) {
            const ulonglong2* rp = (const ulonglong2*)(pool + (j + s) * 20);
            ulonglong2 r0 = rp[0], r1 = rp[1], r2 = rp[2], r3 = rp[3];
            u64 a0 = 0ull, a1 = 0ull;
            a0 = fma2(xq[0], r0.x, a0); a1 = fma2(xq[1], r0.y, a1);
            a0 = fma2(xq[2], r1.x, a0); a1 = fma2(xq[3], r1.y, a1);
            a0 = fma2(xq[4], r2.x, a0); a1 = fma2(xq[5], r2.y, a1);
            a0 = fma2(xq[6], r3.x, a0); a1 = fma2(xq[7], r3.y, a1);
            float l0, h0, l1, h1; upk2(l0, h0, a0); upk2(l1, h1, a1);
            float dot = (l0 + h0) + (l1 + h1);
            dd[s] = n2 + sn2[j + s] - 2.f * dot;
        }
        if (j == t)     dd[0] = 1e30f;
        if (j + 1 == t) dd[1] = 1e30f;
        if (j + 2 == t) dd[2] = 1e30f;
        if (j + 3 == t) dd[3] = 1e30f;
        ins20(kA, embed(dd[0], j));
        ins20(kA, embed(dd[2], j + 2));
        ins20(kB, embed(dd[1], j + 1));
        ins20(kB, embed(dd[3], j + 3));
    }
#pragma unroll
    for (int k = 0; k < KN; ++k)
        nb2[t * KN + k] = (unsigned char)(__float_as_uint(fminf(kA[k], kB[KN - 1 - k])) & 127u);

    // ---- conv2: v2 = x1f@Wv -> smem (stride 33); x2 = u2 + max_k v2[j] ----
    float* v2s = pool + 2560;
    {
        const ulonglong2* cv = (const ulonglong2*)c2v;
        u64 V[16];
#pragma unroll
        for (int g = 0; g < 16; ++g) V[g] = 0ull;
#pragma unroll
        for (int f = 0; f < 16; ++f) {
            u64 hv = pk2(x1f[f], x1f[f]);
#pragma unroll
            for (int g = 0; g < 8; ++g) {
                ulonglong2 wv = cv[f * 8 + g];
                V[2 * g]     = fma2(hv, wv.x, V[2 * g]);
                V[2 * g + 1] = fma2(hv, wv.y, V[2 * g + 1]);
            }
        }
#pragma unroll
        for (int g = 0; g < 16; ++g) {
            float a, bb; upk2(a, bb, V[g]);
            v2s[t * 33 + 2 * g] = a; v2s[t * 33 + 2 * g + 1] = bb;
        }
    }
    __syncthreads();

    float x2m[32];
#pragma unroll
    for (int c = 0; c < 32; ++c) x2m[c] = -1e30f;
#pragma unroll 1
    for (int k = 0; k < KN; ++k) {
        int j = (int)nb2[t * KN + k];
#pragma unroll
        for (int c = 0; c < 32; ++c) x2m[c] = fmaxf(x2m[c], v2s[j * 33 + c]);
    }
    float x2a[32];
    {
        const ulonglong2* cu = (const ulonglong2*)c2u;
        const u64* cbu = (const u64*)c2bs;
        u64 U[16];
#pragma unroll
        for (int g = 0; g < 16; ++g) U[g] = cbu[g];
#pragma unroll
        for (int f = 0; f < 16; ++f) {
            u64 hv = pk2(x1f[f], x1f[f]);
#pragma unroll
            for (int g = 0; g < 8; ++g) {
                ulonglong2 wv = cu[f * 8 + g];
                U[2 * g]     = fma2(hv, wv.x, U[2 * g]);
                U[2 * g + 1] = fma2(hv, wv.y, U[2 * g + 1]);
            }
        }
#pragma unroll
        for (int g = 0; g < 16; ++g) {
            float a, bb; upk2(a, bb, U[g]);
            x2a[2 * g]     = a  + x2m[2 * g];
            x2a[2 * g + 1] = bb + x2m[2 * g + 1];
        }
    }
    __syncthreads();   // all v2/x1s reads done; pool free

    // ---- load lin1 weights transposed: lwt[c][f] = lw[f][c] ----
#pragma unroll 1
    for (int i = t; i < 48 * 128; i += 128) {
        int c = i / 48, f = i - c * 48;
        pool[i] = lw[f * 128 + c];
    }
    __syncthreads();

    // ---- lin1: per-channel broadcast dot + shuffle/cross-warp max (unroll 4) ----
    u64 F2[24];
#pragma unroll
    for (int g = 0; g < 8; ++g)  F2[g]     = pk2(x1f[2 * g], x1f[2 * g + 1]);
#pragma unroll
    for (int g = 0; g < 16; ++g) F2[8 + g] = pk2(x2a[2 * g], x2a[2 * g + 1]);
#pragma unroll 4
    for (int c = 0; c < 128; ++c) {
        const ulonglong2* rw = (const ulonglong2*)(pool + c * 48);
        u64 a0 = 0ull, a1 = 0ull;
#pragma unroll
        for (int g = 0; g < 12; ++g) {
            ulonglong2 wv = rw[g];
            a0 = fma2(F2[2 * g],     wv.x, a0);
            a1 = fma2(F2[2 * g + 1], wv.y, a1);
        }
        float lo, hi; upk2(lo, hi, add2(a0, a1));
        float v = lo + hi;
#pragma unroll
        for (int o = 16; o > 0; o >>= 1)
            v = fmaxf(v, __shfl_xor_sync(0xffffffffu, v, o));
        if (lane == 0) wm[c * 4 + wid] = v;
    }
    __syncthreads();
    gvec[t] = fmaxf(fmaxf(wm[t * 4 + 0], wm[t * 4 + 1]),
                    fmaxf(wm[t * 4 + 2], wm[t * 4 + 3])) + __ldg(lb + t);
    __syncthreads();

    // ---- head MLP 128->64->64->2 + log_softmax ----
    if (t < 64) {
        float a = mb1[t];
#pragma unroll 4
        for (int i = 0; i < 128; ++i) a = fmaf(gvec[i], mw1[i * 64 + t], a);
        h1s[t] = fmaxf(a, 0.f);
    }
    __syncthreads();
    if (t < 64) {
        float a = mb2[t];
#pragma unroll 4
        for (int i = 0; i < 64; ++i) a = fmaf(h1s[i], mw2[i * 64 + t], a);
        h2s[t] = fmaxf(a, 0.f);
    }
    __syncthreads();
    if (t < 2) {
        float a = mb3[t];
#pragma unroll 4
        for (int i = 0; i < 64; ++i) a = fmaf(h2s[i], mw3[i * 2 + t], a);
        outs[t] = a;
    }
    __syncthreads();
    if (t == 0) {
        float o0 = outs[0], o1 = outs[1];
        float m = fmaxf(o0, o1);
        float lse = m + logf(expf(o0 - m) + expf(o1 - m));
        out[b * 2 + 0] = o0 - lse;
        out[b * 2 + 1] = o1 - lse;
    }
}

// ------------------------------------------------------------------
extern "C" void kernel_launch(void* const* d_in, const int* in_sizes, int n_in,
                              void* d_out, int out_size)
{
    (void)in_sizes; (void)n_in; (void)out_size;
    const float* pos   = (const float*)d_in[0];
    const float* c1_w1 = (const float*)d_in[2];
    const float* c1_b1 = (const float*)d_in[3];
    const float* c1_g1 = (const float*)d_in[4];
    const float* c1_be1= (const float*)d_in[5];
    const float* c1_w2 = (const float*)d_in[6];
    const float* c1_b2 = (const float*)d_in[7];
    const float* c1_g2 = (const float*)d_in[8];
    const float* c1_be2= (const float*)d_in[9];
    const float* c1_w3 = (const float*)d_in[10];
    const float* c1_b3 = (const float*)d_in[11];
    const float* c2_w  = (const float*)d_in[12];
    const float* c2_b  = (const float*)d_in[13];
    const float* lw    = (const float*)d_in[14];
    const float* lb    = (const float*)d_in[15];
    const float* m_w1  = (const float*)d_in[16];
    const float* m_b1  = (const float*)d_in[17];
    const float* m_w2  = (const float*)d_in[18];
    const float* m_b2  = (const float*)d_in[19];
    const float* m_w3  = (const float*)d_in[20];
    const float* m_b3  = (const float*)d_in[21];
    float* out = (float*)d_out;

    k0_zero<<<1, 64>>>();
    k1_knn_stats<<<BG, 128>>>(pos, c1_w1, c1_b1);
    k2_stats2<<<BG, 128>>>(pos, c1_w1, c1_b1, c1_g1, c1_be1, c1_w2, c1_b2);
    k3_mega<<<BG, 128>>>(c1_g1, c1_be1, c1_g2, c1_be2,
                         c1_w3, c1_b3,
                         c2_w, c2_b, lw, lb,
                         m_w1, m_b1, m_w2, m_b2, m_w3, m_b3,
                         out);
}

// round 16
// speedup vs baseline: 1.4563x; 1.2102x over previous
#include <cuda_runtime.h>
#include <math.h>

#define BG 1024
#define PP 128
#define KN 20
#define EPSB 1e-5f

typedef unsigned long long u64;

// ---- persistent scratch ----
__device__ unsigned int g_idx1[BG * PP * 5];        // 20 packed neighbor bytes per point
__device__ float g_stats[64];                       // sum1/sq1/sum2/sq2
// A2 buffer, layout [b][e][g][t] in float4 units: warp accesses are 4-line coalesced
__device__ float4 g_a2[(size_t)BG * KN * 4 * PP];

__global__ void k0_zero() { if (threadIdx.x < 64) g_stats[threadIdx.x] = 0.f; }

__device__ __forceinline__ float embed(float d2, int j) {
    return __uint_as_float((__float_as_uint(d2) & 0xFFFFFF80u) | (unsigned)j);
}
__device__ __forceinline__ u64 pk2(float a, float b) {
    u64 r; asm("mov.b64 %0,{%1,%2};" : "=l"(r) : "f"(a), "f"(b)); return r;
}
__device__ __forceinline__ void upk2(float& a, float& b, u64 v) {
    asm("mov.b64 {%0,%1},%2;" : "=f"(a), "=f"(b) : "l"(v));
}
__device__ __forceinline__ u64 fma2(u64 a, u64 b, u64 c) {
    u64 d; asm("fma.rn.f32x2 %0,%1,%2,%3;" : "=l"(d) : "l"(a), "l"(b), "l"(c)); return d;
}
__device__ __forceinline__ u64 add2(u64 a, u64 b) {
    u64 d; asm("add.rn.f32x2 %0,%1,%2;" : "=l"(d) : "l"(a), "l"(b)); return d;
}
__device__ __forceinline__ void ins20(float (&kd)[KN], float dv) {
    kd[KN - 1] = fminf(kd[KN - 1], dv);
#pragma unroll
    for (int p = KN - 1; p > 0; --p) {
        float lo = fminf(kd[p - 1], kd[p]);
        float hi = fmaxf(kd[p - 1], kd[p]);
        kd[p - 1] = lo; kd[p] = hi;
    }
}

// ------------------------------------------------------------------
// K1: kNN on pos (2 lists, 4 cand/iter) + factored BN1 pre-activation stats
__global__ __launch_bounds__(128) void k1_knn_stats(
    const float* __restrict__ pos,
    const float* __restrict__ w1, const float* __restrict__ b1)
{
    __shared__ float spx[PP], spy[PP], spz[PP], sn[PP];
    __shared__ float v1s[PP * 17];
    __shared__ float w1u[48], w1v[48], b1s[16];
    __shared__ float wpart[4][32];

    int b = blockIdx.x, t = threadIdx.x;
    float px = pos[(b * PP + t) * 3 + 0];
    float py = pos[(b * PP + t) * 3 + 1];
    float pz = pos[(b * PP + t) * 3 + 2];
    spx[t] = px; spy[t] = py; spz[t] = pz;
    if (t < 48) { w1u[t] = w1[t] - w1[t + 48]; w1v[t] = w1[t + 48]; }
    if (t < 16) b1s[t] = b1[t];
    float ni = px * px + py * py + pz * pz;
    sn[t] = ni;
    __syncthreads();

    float kA[KN], kB[KN];
#pragma unroll
    for (int k = 0; k < KN; ++k) { kA[k] = 1e38f; kB[k] = 1e38f; }
#pragma unroll 1
    for (int j = 0; j < PP; j += 4) {
        float d0 = ni + sn[j]     - 2.f * (px * spx[j]     + py * spy[j]     + pz * spz[j]);
        float d1 = ni + sn[j + 1] - 2.f * (px * spx[j + 1] + py * spy[j + 1] + pz * spz[j + 1]);
        float d2 = ni + sn[j + 2] - 2.f * (px * spx[j + 2] + py * spy[j + 2] + pz * spz[j + 2]);
        float d3 = ni + sn[j + 3] - 2.f * (px * spx[j + 3] + py * spy[j + 3] + pz * spz[j + 3]);
        if (j == t)     d0 = 1e30f;
        if (j + 1 == t) d1 = 1e30f;
        if (j + 2 == t) d2 = 1e30f;
        if (j + 3 == t) d3 = 1e30f;
        ins20(kA, embed(d0, j));
        ins20(kA, embed(d2, j + 2));
        ins20(kB, embed(d1, j + 1));
        ins20(kB, embed(d3, j + 3));
    }

    float u1[16];
#pragma unroll
    for (int c = 0; c < 16; ++c) {
        u1[c] = b1s[c] + px * w1u[c] + py * w1u[16 + c] + pz * w1u[32 + c];
        v1s[t * 17 + c] = px * w1v[c] + py * w1v[16 + c] + pz * w1v[32 + c];
    }
    __syncthreads();

    unsigned ji[KN];
#pragma unroll
    for (int i = 0; i < KN; ++i)
        ji[i] = __float_as_uint(fminf(kA[i], kB[KN - 1 - i])) & 127u;
    unsigned* oi = g_idx1 + ((size_t)b * PP + t) * 5;
#pragma unroll
    for (int w = 0; w < 5; ++w)
        oi[w] = ji[4 * w] | (ji[4 * w + 1] << 8) | (ji[4 * w + 2] << 16) | (ji[4 * w + 3] << 24);

    // factored stats: sum h = 20u + Sv ; sum h^2 = 20u^2 + 2u*Sv + Sq
    float Sv[16], Sq[16];
#pragma unroll
    for (int c = 0; c < 16; ++c) { Sv[c] = 0.f; Sq[c] = 0.f; }
#pragma unroll
    for (int k = 0; k < KN; ++k) {
        int j = (int)ji[k];
#pragma unroll
        for (int c = 0; c < 16; ++c) {
            float v = v1s[j * 17 + c];
            Sv[c] += v; Sq[c] = fmaf(v, v, Sq[c]);
        }
    }
    float s[16], q[16];
#pragma unroll
    for (int c = 0; c < 16; ++c) {
        float u = u1[c];
        s[c] = fmaf(20.f, u, Sv[c]);
        q[c] = fmaf(20.f * u, u, fmaf(2.f * u, Sv[c], Sq[c]));
    }
#pragma unroll
    for (int c = 0; c < 16; ++c) {
        for (int o = 16; o > 0; o >>= 1) {
            s[c] += __shfl_xor_sync(0xffffffffu, s[c], o);
            q[c] += __shfl_xor_sync(0xffffffffu, q[c], o);
        }
    }
    int lane = t & 31, wid = t >> 5;
    if (lane == 0) {
#pragma unroll
        for (int c = 0; c < 16; ++c) { wpart[wid][c] = s[c]; wpart[wid][16 + c] = q[c]; }
    }
    __syncthreads();
    if (t < 32) {
        float v = wpart[0][t] + wpart[1][t] + wpart[2][t] + wpart[3][t];
        atomicAdd(&g_stats[t], v);
    }
}

// ------------------------------------------------------------------
// K2: h1 = relu(u1'+v1') (BN1 folded); A2 = h1@W2+b2 -> stats AND coalesced store
__global__ __launch_bounds__(128) void k2_stats2(
    const float* __restrict__ pos,
    const float* __restrict__ w1, const float* __restrict__ b1,
    const float* __restrict__ g1, const float* __restrict__ be1,
    const float* __restrict__ w2, const float* __restrict__ b2)
{
    __shared__ float v1s[PP * 17];
    __shared__ float w1u[48], w1v[48], b1s[16];
    __shared__ __align__(16) float sw2[256];
    __shared__ __align__(16) float sb2[16];
    __shared__ float bn1s[16], bn1o[16];
    __shared__ float wpart[4][32];

    int b = blockIdx.x, t = threadIdx.x;
    float px = pos[(b * PP + t) * 3 + 0];
    float py = pos[(b * PP + t) * 3 + 1];
    float pz = pos[(b * PP + t) * 3 + 2];
    if (t < 48) { w1u[t] = w1[t] - w1[t + 48]; w1v[t] = w1[t + 48]; }
    if (t < 16) b1s[t] = b1[t];
    sw2[t] = w2[t]; sw2[t + 128] = w2[t + 128];
    if (t < 16) sb2[t] = b2[t];
    if (t >= 32 && t < 48) {
        int c = t - 32;
        const float N = (float)BG * PP * KN;
        float m = g_stats[c] / N;
        float v = g_stats[16 + c] / N - m * m;
        float sc = g1[c] * rsqrtf(v + EPSB);
        bn1s[c] = sc; bn1o[c] = be1[c] - m * sc;
    }
    __syncthreads();

    float u1[16];
#pragma unroll
    for (int c = 0; c < 16; ++c) {
        float uu = b1s[c] + px * w1u[c] + py * w1u[16 + c] + pz * w1u[32 + c];
        float vv = px * w1v[c] + py * w1v[16 + c] + pz * w1v[32 + c];
        u1[c] = fmaf(uu, bn1s[c], bn1o[c]);
        v1s[t * 17 + c] = vv * bn1s[c];
    }
    __syncthreads();

    const unsigned* oi = g_idx1 + ((size_t)b * PP + t) * 5;
    const ulonglong2* sw2u2 = (const ulonglong2*)sw2;
    const u64* sb2u = (const u64*)sb2;
    float4* gaB = g_a2 + (size_t)b * KN * 4 * PP;   // [e][g][t]

    u64 S[8], Q[8];
#pragma unroll
    for (int g = 0; g < 8; ++g) { S[g] = 0ull; Q[g] = 0ull; }
#pragma unroll 1
    for (int w = 0; w < 5; ++w) {
        unsigned pk = oi[w];
#pragma unroll 1
        for (int kk = 0; kk < 4; ++kk) {
            int j = (int)(pk & 255u); pk >>= 8;
            float h1[16];
#pragma unroll
            for (int c = 0; c < 16; ++c)
                h1[c] = fmaxf(u1[c] + v1s[j * 17 + c], 0.f);
            u64 A2[8];
#pragma unroll
            for (int g = 0; g < 8; ++g) A2[g] = sb2u[g];
#pragma unroll
            for (int f = 0; f < 16; ++f) {
                u64 hv = pk2(h1[f], h1[f]);
                ulonglong2 w0 = sw2u2[f * 4 + 0], w1q = sw2u2[f * 4 + 1];
                ulonglong2 w2q = sw2u2[f * 4 + 2], w3q = sw2u2[f * 4 + 3];
                A2[0] = fma2(hv, w0.x, A2[0]);  A2[1] = fma2(hv, w0.y, A2[1]);
                A2[2] = fma2(hv, w1q.x, A2[2]); A2[3] = fma2(hv, w1q.y, A2[3]);
                A2[4] = fma2(hv, w2q.x, A2[4]); A2[5] = fma2(hv, w2q.y, A2[5]);
                A2[6] = fma2(hv, w3q.x, A2[6]); A2[7] = fma2(hv, w3q.y, A2[7]);
            }
            // coalesced store: [e][g][t]
            {
                int e = w * 4 + kk;
                float a0, a1, a2, a3;
#pragma unroll
                for (int g = 0; g < 4; ++g) {
                    upk2(a0, a1, A2[2 * g]); upk2(a2, a3, A2[2 * g + 1]);
                    gaB[((size_t)e * 4 + g) * PP + t] = make_float4(a0, a1, a2, a3);
                }
            }
#pragma unroll
            for (int g = 0; g < 8; ++g) {
                S[g] = add2(S[g], A2[g]);
                Q[g] = fma2(A2[g], A2[g], Q[g]);
            }
        }
    }
    float s[16], q[16];
#pragma unroll
    for (int g = 0; g < 8; ++g) {
        upk2(s[2 * g], s[2 * g + 1], S[g]);
        upk2(q[2 * g], q[2 * g + 1], Q[g]);
    }
#pragma unroll
    for (int c = 0; c < 16; ++c) {
        for (int o = 16; o > 0; o >>= 1) {
            s[c] += __shfl_xor_sync(0xffffffffu, s[c], o);
            q[c] += __shfl_xor_sync(0xffffffffu, q[c], o);
        }
    }
    int lane = t & 31, wid = t >> 5;
    if (lane == 0) {
#pragma unroll
        for (int c = 0; c < 16; ++c) { wpart[wid][c] = s[c]; wpart[wid][16 + c] = q[c]; }
    }
    __syncthreads();
    if (t < 32) {
        float v = wpart[0][t] + wpart[1][t] + wpart[2][t] + wpart[3][t];
        atomicAdd(&g_stats[32 + t], v);
    }
}

// ------------------------------------------------------------------
// K3: conv1 from precomputed A2 (coalesced stream, bn2-relu, W3 GEMV, max)
//     -> x1 ; kNN2 ; conv2 ; lin1 ; head
__global__ __launch_bounds__(128, 1) void k3_mega(
    const float* __restrict__ g1, const float* __restrict__ be1,
    const float* __restrict__ g2, const float* __restrict__ be2,
    const float* __restrict__ w3, const float* __restrict__ b3,
    const float* __restrict__ c2w, const float* __restrict__ c2b,
    const float* __restrict__ lw,  const float* __restrict__ lb,
    const float* __restrict__ mw1, const float* __restrict__ mb1,
    const float* __restrict__ mw2, const float* __restrict__ mb2,
    const float* __restrict__ mw3, const float* __restrict__ mb3,
    float* __restrict__ out)
{
    __shared__ __align__(16) float pool[6784];
    __shared__ float sn2[PP];
    __shared__ unsigned char nb2[PP * KN];
    __shared__ __align__(16) float sw3[256];
    __shared__ float sb3[16], bn2s[16], bn2o[16];
    __shared__ __align__(16) float c2u[512];
    __shared__ __align__(16) float c2v[512];
    __shared__ __align__(16) float c2bs[32];
    __shared__ float wm[128 * 4];
    __shared__ float gvec[128], h1s[64], h2s[64], outs[2];

    int b = blockIdx.x, t = threadIdx.x;
    int lane = t & 31, wid = t >> 5;
    if (t < 16) sb3[t] = b3[t];
    sw3[t] = w3[t]; sw3[t + 128] = w3[t + 128];
#pragma unroll
    for (int i = t; i < 512; i += 128) { c2u[i] = c2w[i] - c2w[i + 512]; c2v[i] = c2w[i + 512]; }
    if (t < 32) c2bs[t] = c2b[t];
    if (t >= 80 && t < 96) {
        int c = t - 80;
        const float N = (float)BG * PP * KN;
        float m = g_stats[32 + c] / N;
        float v = g_stats[48 + c] / N - m * m;
        float sc = g2[c] * rsqrtf(v + EPSB);
        bn2s[c] = sc; bn2o[c] = be2[c] - m * sc;
    }
    __syncthreads();   // weights + bn2 consts ready

    // ---- conv1: coalesced stream of A2 [e][g][t], bn2-relu, GEMV W3, max ----
    const ulonglong2* sw3u2 = (const ulonglong2*)sw3;
    const float4* gaB = g_a2 + (size_t)b * KN * 4 * PP;
    float x1a[16];
#pragma unroll
    for (int c = 0; c < 16; ++c) x1a[c] = -1e30f;
#pragma unroll 1
    for (int k = 0; k < KN; ++k) {
        float4 e0 = gaB[((size_t)k * 4 + 0) * PP + t];
        float4 e1 = gaB[((size_t)k * 4 + 1) * PP + t];
        float4 e2 = gaB[((size_t)k * 4 + 2) * PP + t];
        float4 e3 = gaB[((size_t)k * 4 + 3) * PP + t];
        float h2v[16];
        h2v[0]  = fmaxf(fmaf(e0.x, bn2s[0],  bn2o[0]),  0.f);
        h2v[1]  = fmaxf(fmaf(e0.y, bn2s[1],  bn2o[1]),  0.f);
        h2v[2]  = fmaxf(fmaf(e0.z, bn2s[2],  bn2o[2]),  0.f);
        h2v[3]  = fmaxf(fmaf(e0.w, bn2s[3],  bn2o[3]),  0.f);
        h2v[4]  = fmaxf(fmaf(e1.x, bn2s[4],  bn2o[4]),  0.f);
        h2v[5]  = fmaxf(fmaf(e1.y, bn2s[5],  bn2o[5]),  0.f);
        h2v[6]  = fmaxf(fmaf(e1.z, bn2s[6],  bn2o[6]),  0.f);
        h2v[7]  = fmaxf(fmaf(e1.w, bn2s[7],  bn2o[7]),  0.f);
        h2v[8]  = fmaxf(fmaf(e2.x, bn2s[8],  bn2o[8]),  0.f);
        h2v[9]  = fmaxf(fmaf(e2.y, bn2s[9],  bn2o[9]),  0.f);
        h2v[10] = fmaxf(fmaf(e2.z, bn2s[10], bn2o[10]), 0.f);
        h2v[11] = fmaxf(fmaf(e2.w, bn2s[11], bn2o[11]), 0.f);
        h2v[12] = fmaxf(fmaf(e3.x, bn2s[12], bn2o[12]), 0.f);
        h2v[13] = fmaxf(fmaf(e3.y, bn2s[13], bn2o[13]), 0.f);
        h2v[14] = fmaxf(fmaf(e3.z, bn2s[14], bn2o[14]), 0.f);
        h2v[15] = fmaxf(fmaf(e3.w, bn2s[15], bn2o[15]), 0.f);

        u64 A3[8];
#pragma unroll
        for (int g = 0; g < 8; ++g) A3[g] = 0ull;
#pragma unroll
        for (int f = 0; f < 16; ++f) {
            u64 hv = pk2(h2v[f], h2v[f]);
            ulonglong2 w0 = sw3u2[f * 4 + 0], w1q = sw3u2[f * 4 + 1];
            ulonglong2 w2q = sw3u2[f * 4 + 2], w3q = sw3u2[f * 4 + 3];
            A3[0] = fma2(hv, w0.x, A3[0]);  A3[1] = fma2(hv, w0.y, A3[1]);
            A3[2] = fma2(hv, w1q.x, A3[2]); A3[3] = fma2(hv, w1q.y, A3[3]);
            A3[4] = fma2(hv, w2q.x, A3[4]); A3[5] = fma2(hv, w2q.y, A3[5]);
            A3[6] = fma2(hv, w3q.x, A3[6]); A3[7] = fma2(hv, w3q.y, A3[7]);
        }
#pragma unroll
        for (int g = 0; g < 8; ++g) {
            float a, bb; upk2(a, bb, A3[g]);
            x1a[2 * g]     = fmaxf(x1a[2 * g],     a);
            x1a[2 * g + 1] = fmaxf(x1a[2 * g + 1], bb);
        }
    }
    float x1f[16];
    float n2 = 0.f;
#pragma unroll
    for (int c = 0; c < 16; ++c) { x1f[c] = x1a[c] + sb3[c]; n2 = fmaf(x1f[c], x1f[c], n2); }
    {
        float4* xr = (float4*)pool + t * 5;
#pragma unroll
        for (int g = 0; g < 4; ++g)
            xr[g] = make_float4(x1f[4 * g], x1f[4 * g + 1], x1f[4 * g + 2], x1f[4 * g + 3]);
        sn2[t] = n2;
    }
    __syncthreads();

    // ---- kNN2: 4 candidates/iter, packed f32x2 dots, 2 inserts per list ----
    u64 xq[8];
#pragma unroll
    for (int g = 0; g < 8; ++g) xq[g] = pk2(x1f[2 * g], x1f[2 * g + 1]);

    float kA[KN], kB[KN];
#pragma unroll
    for (int k = 0; k < KN; ++k) { kA[k] = 1e38f; kB[k] = 1e38f; }
#pragma unroll 1
    for (int j = 0; j < PP; j += 4) {
        float dd[4];
#pragma unroll
        for (int s = 0; s < 4; ++s) {
            const ulonglong2* rp = (const ulonglong2*)(pool + (j + s) * 20);
            ulonglong2 r0 = rp[0], r1 = rp[1], r2 = rp[2], r3 = rp[3];
            u64 a0 = 0ull, a1 = 0ull;
            a0 = fma2(xq[0], r0.x, a0); a1 = fma2(xq[1], r0.y, a1);
            a0 = fma2(xq[2], r1.x, a0); a1 = fma2(xq[3], r1.y, a1);
            a0 = fma2(xq[4], r2.x, a0); a1 = fma2(xq[5], r2.y, a1);
            a0 = fma2(xq[6], r3.x, a0); a1 = fma2(xq[7], r3.y, a1);
            float l0, h0, l1, h1; upk2(l0, h0, a0); upk2(l1, h1, a1);
            float dot = (l0 + h0) + (l1 + h1);
            dd[s] = n2 + sn2[j + s] - 2.f * dot;
        }
        if (j == t)     dd[0] = 1e30f;
        if (j + 1 == t) dd[1] = 1e30f;
        if (j + 2 == t) dd[2] = 1e30f;
        if (j + 3 == t) dd[3] = 1e30f;
        ins20(kA, embed(dd[0], j));
        ins20(kA, embed(dd[2], j + 2));
        ins20(kB, embed(dd[1], j + 1));
        ins20(kB, embed(dd[3], j + 3));
    }
#pragma unroll
    for (int k = 0; k < KN; ++k)
        nb2[t * KN + k] = (unsigned char)(__float_as_uint(fminf(kA[k], kB[KN - 1 - k])) & 127u);

    // ---- conv2: v2 = x1f@Wv -> smem (stride 33); x2 = u2 + max_k v2[j] ----
    float* v2s = pool + 2560;
    {
        const ulonglong2* cv = (const ulonglong2*)c2v;
        u64 V[16];
#pragma unroll
        for (int g = 0; g < 16; ++g) V[g] = 0ull;
#pragma unroll
        for (int f = 0; f < 16; ++f) {
            u64 hv = pk2(x1f[f], x1f[f]);
#pragma unroll
            for (int g = 0; g < 8; ++g) {
                ulonglong2 wv = cv[f * 8 + g];
                V[2 * g]     = fma2(hv, wv.x, V[2 * g]);
                V[2 * g + 1] = fma2(hv, wv.y, V[2 * g + 1]);
            }
        }
#pragma unroll
        for (int g = 0; g < 16; ++g) {
            float a, bb; upk2(a, bb, V[g]);
            v2s[t * 33 + 2 * g] = a; v2s[t * 33 + 2 * g + 1] = bb;
        }
    }
    __syncthreads();

    float x2m[32];
#pragma unroll
    for (int c = 0; c < 32; ++c) x2m[c] = -1e30f;
#pragma unroll 1
    for (int k = 0; k < KN; ++k) {
        int j = (int)nb2[t * KN + k];
#pragma unroll
        for (int c = 0; c < 32; ++c) x2m[c] = fmaxf(x2m[c], v2s[j * 33 + c]);
    }
    float x2a[32];
    {
        const ulonglong2* cu = (const ulonglong2*)c2u;
        const u64* cbu = (const u64*)c2bs;
        u64 U[16];
#pragma unroll
        for (int g = 0; g < 16; ++g) U[g] = cbu[g];
#pragma unroll
        for (int f = 0; f < 16; ++f) {
            u64 hv = pk2(x1f[f], x1f[f]);
#pragma unroll
            for (int g = 0; g < 8; ++g) {
                ulonglong2 wv = cu[f * 8 + g];
                U[2 * g]     = fma2(hv, wv.x, U[2 * g]);
                U[2 * g + 1] = fma2(hv, wv.y, U[2 * g + 1]);
            }
        }
#pragma unroll
        for (int g = 0; g < 16; ++g) {
            float a, bb; upk2(a, bb, U[g]);
            x2a[2 * g]     = a  + x2m[2 * g];
            x2a[2 * g + 1] = bb + x2m[2 * g + 1];
        }
    }
    __syncthreads();   // all v2/x1s reads done; pool free

    // ---- load lin1 weights transposed: lwt[c][f] = lw[f][c] ----
#pragma unroll 1
    for (int i = t; i < 48 * 128; i += 128) {
        int c = i / 48, f = i - c * 48;
        pool[i] = lw[f * 128 + c];
    }
    __syncthreads();

    // ---- lin1: per-channel broadcast dot + shuffle/cross-warp max (unroll 4) ----
    u64 F2[24];
#pragma unroll
    for (int g = 0; g < 8; ++g)  F2[g]     = pk2(x1f[2 * g], x1f[2 * g + 1]);
#pragma unroll
    for (int g = 0; g < 16; ++g) F2[8 + g] = pk2(x2a[2 * g], x2a[2 * g + 1]);
#pragma unroll 4
    for (int c = 0; c < 128; ++c) {
        const ulonglong2* rw = (const ulonglong2*)(pool + c * 48);
        u64 a0 = 0ull, a1 = 0ull;
#pragma unroll
        for (int g = 0; g < 12; ++g) {
            ulonglong2 wv = rw[g];
            a0 = fma2(F2[2 * g],     wv.x, a0);
            a1 = fma2(F2[2 * g + 1], wv.y, a1);
        }
        float lo, hi; upk2(lo, hi, add2(a0, a1));
        float v = lo + hi;
#pragma unroll
        for (int o = 16; o > 0; o >>= 1)
            v = fmaxf(v, __shfl_xor_sync(0xffffffffu, v, o));
        if (lane == 0) wm[c * 4 + wid] = v;
    }
    __syncthreads();
    gvec[t] = fmaxf(fmaxf(wm[t * 4 + 0], wm[t * 4 + 1]),
                    fmaxf(wm[t * 4 + 2], wm[t * 4 + 3])) + __ldg(lb + t);
    __syncthreads();

    // ---- head MLP 128->64->64->2 + log_softmax ----
    if (t < 64) {
        float a = mb1[t];
#pragma unroll 4
        for (int i = 0; i < 128; ++i) a = fmaf(gvec[i], mw1[i * 64 + t], a);
        h1s[t] = fmaxf(a, 0.f);
    }
    __syncthreads();
    if (t < 64) {
        float a = mb2[t];
#pragma unroll 4
        for (int i = 0; i < 64; ++i) a = fmaf(h1s[i], mw2[i * 64 + t], a);
        h2s[t] = fmaxf(a, 0.f);
    }
    __syncthreads();
    if (t < 2) {
        float a = mb3[t];
#pragma unroll 4
        for (int i = 0; i < 64; ++i) a = fmaf(h2s[i], mw3[i * 2 + t], a);
        outs[t] = a;
    }
    __syncthreads();
    if (t == 0) {
        float o0 = outs[0], o1 = outs[1];
        float m = fmaxf(o0, o1);
        float lse = m + logf(expf(o0 - m) + expf(o1 - m));
        out[b * 2 + 0] = o0 - lse;
        out[b * 2 + 1] = o1 - lse;
    }
}

// ------------------------------------------------------------------
extern "C" void kernel_launch(void* const* d_in, const int* in_sizes, int n_in,
                              void* d_out, int out_size)
{
    (void)in_sizes; (void)n_in; (void)out_size;
    const float* pos   = (const float*)d_in[0];
    const float* c1_w1 = (const float*)d_in[2];
    const float* c1_b1 = (const float*)d_in[3];
    const float* c1_g1 = (const float*)d_in[4];
    const float* c1_be1= (const float*)d_in[5];
    const float* c1_w2 = (const float*)d_in[6];
    const float* c1_b2 = (const float*)d_in[7];
    const float* c1_g2 = (const float*)d_in[8];
    const float* c1_be2= (const float*)d_in[9];
    const float* c1_w3 = (const float*)d_in[10];
    const float* c1_b3 = (const float*)d_in[11];
    const float* c2_w  = (const float*)d_in[12];
    const float* c2_b  = (const float*)d_in[13];
    const float* lw    = (const float*)d_in[14];
    const float* lb    = (const float*)d_in[15];
    const float* m_w1  = (const float*)d_in[16];
    const float* m_b1  = (const float*)d_in[17];
    const float* m_w2  = (const float*)d_in[18];
    const float* m_b2  = (const float*)d_in[19];
    const float* m_w3  = (const float*)d_in[20];
    const float* m_b3  = (const float*)d_in[21];
    float* out = (float*)d_out;

    k0_zero<<<1, 64>>>();
    k1_knn_stats<<<BG, 128>>>(pos, c1_w1, c1_b1);
    k2_stats2<<<BG, 128>>>(pos, c1_w1, c1_b1, c1_g1, c1_be1, c1_w2, c1_b2);
    k3_mega<<<BG, 128>>>(c1_g1, c1_be1, c1_g2, c1_be2,
                         c1_w3, c1_b3,
                         c2_w, c2_b, lw, lb,
                         m_w1, m_b1, m_w2, m_b2, m_w3, m_b3,
                         out);
}